// round 1
// baseline (speedup 1.0000x reference)
#include <cuda_runtime.h>
#include <cuda_bf16.h>
#include <math.h>

// Problem constants
#define BATCH 8
#define SEQ   1024
#define HID   1024
#define NHEAD 16
#define HDIM  64
#define MROWS (BATCH * SEQ)   // 8192

// ---------------------------------------------------------------------------
// Scratch (device globals; no allocation allowed)
// ---------------------------------------------------------------------------
__device__ float g_Q[MROWS * HID];
__device__ float g_K[MROWS * HID];
__device__ float g_V[MROWS * HID];
__device__ float g_C[MROWS * HID];

// ---------------------------------------------------------------------------
// SGEMM: C[M,N] = A[M,K] @ W[K,N] + bias[N]
// 128x128 block tile, K-tile 8, 256 threads, 8x8 per-thread micro-tile.
// M=8192, N=1024, K=1024 (all exact multiples; no bounds checks).
// ---------------------------------------------------------------------------
#define BM 128
#define BN 128
#define BK 8

__global__ __launch_bounds__(256, 2)
void sgemm_bias(const float* __restrict__ A,
                const float* __restrict__ W,
                const float* __restrict__ bias,
                float* __restrict__ C,
                int M, int N, int K)
{
    __shared__ float As[BK][BM + 4];   // padded to kill cross-kk bank conflicts
    __shared__ float Bs[BK][BN];

    const int bx = blockIdx.x;        // N tile
    const int by = blockIdx.y;        // M tile
    const int tid = threadIdx.x;
    const int tx = tid % 16;
    const int ty = tid / 16;

    // A tile loads: 128 rows x 8 cols = 256 float4 (one per thread)
    const int a_row  = tid >> 1;          // 0..127
    const int a_col4 = (tid & 1) * 4;     // 0 or 4
    // B tile loads: 8 rows x 128 cols = 256 float4 (one per thread)
    const int b_row  = tid >> 5;          // 0..7
    const int b_col4 = (tid & 31) * 4;    // 0..124

    const float* Aptr = A + (size_t)(by * BM + a_row) * K + a_col4;
    const float* Bptr = W + (size_t)b_row * N + bx * BN + b_col4;

    float acc[8][8];
    #pragma unroll
    for (int i = 0; i < 8; i++)
        #pragma unroll
        for (int j = 0; j < 8; j++) acc[i][j] = 0.0f;

    for (int k0 = 0; k0 < K; k0 += BK) {
        float4 av = *(const float4*)(Aptr + k0);
        float4 bv = *(const float4*)(Bptr + (size_t)k0 * N);
        As[a_col4 + 0][a_row] = av.x;
        As[a_col4 + 1][a_row] = av.y;
        As[a_col4 + 2][a_row] = av.z;
        As[a_col4 + 3][a_row] = av.w;
        *(float4*)&Bs[b_row][b_col4] = bv;
        __syncthreads();

        #pragma unroll
        for (int kk = 0; kk < BK; kk++) {
            float a_frag[8], b_frag[8];
            *(float4*)&a_frag[0] = *(const float4*)&As[kk][ty * 8];
            *(float4*)&a_frag[4] = *(const float4*)&As[kk][ty * 8 + 4];
            *(float4*)&b_frag[0] = *(const float4*)&Bs[kk][tx * 8];
            *(float4*)&b_frag[4] = *(const float4*)&Bs[kk][tx * 8 + 4];
            #pragma unroll
            for (int i = 0; i < 8; i++)
                #pragma unroll
                for (int j = 0; j < 8; j++)
                    acc[i][j] = fmaf(a_frag[i], b_frag[j], acc[i][j]);
        }
        __syncthreads();
    }

    // Epilogue: add bias, vectorized stores
    const int row0 = by * BM + ty * 8;
    const int col0 = bx * BN + tx * 8;
    float bfr[8];
    *(float4*)&bfr[0] = *(const float4*)&bias[col0];
    *(float4*)&bfr[4] = *(const float4*)&bias[col0 + 4];
    #pragma unroll
    for (int i = 0; i < 8; i++) {
        float4 r0, r1;
        r0.x = acc[i][0] + bfr[0]; r0.y = acc[i][1] + bfr[1];
        r0.z = acc[i][2] + bfr[2]; r0.w = acc[i][3] + bfr[3];
        r1.x = acc[i][4] + bfr[4]; r1.y = acc[i][5] + bfr[5];
        r1.z = acc[i][6] + bfr[6]; r1.w = acc[i][7] + bfr[7];
        float* crow = C + (size_t)(row0 + i) * N + col0;
        *(float4*)crow       = r0;
        *(float4*)(crow + 4) = r1;
    }
}

// ---------------------------------------------------------------------------
// Fused flash attention: one thread = one query row.
// Block = 64 threads = 64 queries. Grid = (S/64, NHEAD, BATCH).
// Q row + output accumulator + 64-score tile in registers; K/V tiles (64x64)
// in shared memory, read via broadcast float4.
// ---------------------------------------------------------------------------
#define QT 64
#define KT 64

__global__ __launch_bounds__(64)
void flash_attn(const float* __restrict__ Q,
                const float* __restrict__ K,
                const float* __restrict__ V,
                float* __restrict__ O)
{
    __shared__ float Ks[KT][HDIM];
    __shared__ float Vs[KT][HDIM];

    const int q0 = blockIdx.x * QT;
    const int h  = blockIdx.y;
    const int b  = blockIdx.z;
    const int t  = threadIdx.x;          // query index within the tile

    const float* qptr = Q + ((size_t)(b * SEQ + q0 + t)) * HID + h * HDIM;
    float q[HDIM];
    #pragma unroll
    for (int i = 0; i < HDIM / 4; i++)
        *(float4*)&q[i * 4] = *(const float4*)(qptr + i * 4);

    float o[HDIM];
    #pragma unroll
    for (int d = 0; d < HDIM; d++) o[d] = 0.0f;
    float m = -INFINITY;
    float l = 0.0f;

    for (int k0 = 0; k0 < SEQ; k0 += KT) {
        // Cooperative load of K/V tiles (coalesced float4)
        const float* kbase = K + ((size_t)(b * SEQ + k0)) * HID + h * HDIM;
        const float* vbase = V + ((size_t)(b * SEQ + k0)) * HID + h * HDIM;
        #pragma unroll
        for (int i = 0; i < 16; i++) {
            int idx = i * 64 + t;            // float4 index 0..1023
            int row = idx >> 4;              // 0..63
            int c4  = (idx & 15) * 4;        // 0..60
            *(float4*)&Ks[row][c4] = *(const float4*)(kbase + (size_t)row * HID + c4);
            *(float4*)&Vs[row][c4] = *(const float4*)(vbase + (size_t)row * HID + c4);
        }
        __syncthreads();

        // Scores for this tile
        float s[KT];
        #pragma unroll 4
        for (int j = 0; j < KT; j++) {
            float a0 = 0.0f, a1 = 0.0f;
            #pragma unroll
            for (int d4 = 0; d4 < HDIM; d4 += 8) {
                float4 k0v = *(const float4*)&Ks[j][d4];
                float4 k1v = *(const float4*)&Ks[j][d4 + 4];
                a0 = fmaf(q[d4 + 0], k0v.x, a0);
                a0 = fmaf(q[d4 + 1], k0v.y, a0);
                a0 = fmaf(q[d4 + 2], k0v.z, a0);
                a0 = fmaf(q[d4 + 3], k0v.w, a0);
                a1 = fmaf(q[d4 + 4], k1v.x, a1);
                a1 = fmaf(q[d4 + 5], k1v.y, a1);
                a1 = fmaf(q[d4 + 6], k1v.z, a1);
                a1 = fmaf(q[d4 + 7], k1v.w, a1);
            }
            s[j] = (a0 + a1) * 0.125f;       // 1/sqrt(64)
        }

        // Online softmax (one rescale per tile)
        float mt = m;
        #pragma unroll
        for (int j = 0; j < KT; j++) mt = fmaxf(mt, s[j]);
        float factor = __expf(m - mt);
        m = mt;
        float lsum = 0.0f;
        #pragma unroll
        for (int j = 0; j < KT; j++) {
            s[j] = __expf(s[j] - m);
            lsum += s[j];
        }
        l = l * factor + lsum;
        #pragma unroll
        for (int d = 0; d < HDIM; d++) o[d] *= factor;

        // O += P @ V
        #pragma unroll 4
        for (int j = 0; j < KT; j++) {
            float p = s[j];
            #pragma unroll
            for (int d4 = 0; d4 < HDIM; d4 += 4) {
                float4 vv = *(const float4*)&Vs[j][d4];
                o[d4 + 0] = fmaf(p, vv.x, o[d4 + 0]);
                o[d4 + 1] = fmaf(p, vv.y, o[d4 + 1]);
                o[d4 + 2] = fmaf(p, vv.z, o[d4 + 2]);
                o[d4 + 3] = fmaf(p, vv.w, o[d4 + 3]);
            }
        }
        __syncthreads();
    }

    const float inv = 1.0f / l;
    float* optr = O + ((size_t)(b * SEQ + q0 + t)) * HID + h * HDIM;
    #pragma unroll
    for (int i = 0; i < HDIM / 4; i++) {
        float4 r;
        r.x = o[i * 4 + 0] * inv;
        r.y = o[i * 4 + 1] * inv;
        r.z = o[i * 4 + 2] * inv;
        r.w = o[i * 4 + 3] * inv;
        *(float4*)(optr + i * 4) = r;
    }
}

// ---------------------------------------------------------------------------
// Launch
// ---------------------------------------------------------------------------
extern "C" void kernel_launch(void* const* d_in, const int* in_sizes, int n_in,
                              void* d_out, int out_size)
{
    const float* x  = (const float*)d_in[0];
    const float* Wq = (const float*)d_in[1];
    const float* bq = (const float*)d_in[2];
    const float* Wk = (const float*)d_in[3];
    const float* bk = (const float*)d_in[4];
    const float* Wv = (const float*)d_in[5];
    const float* bv = (const float*)d_in[6];
    const float* Wo = (const float*)d_in[7];
    const float* bo = (const float*)d_in[8];
    float* out = (float*)d_out;

    float *pQ, *pK, *pV, *pC;
    cudaGetSymbolAddress((void**)&pQ, g_Q);
    cudaGetSymbolAddress((void**)&pK, g_K);
    cudaGetSymbolAddress((void**)&pV, g_V);
    cudaGetSymbolAddress((void**)&pC, g_C);

    dim3 ggrid(HID / BN, MROWS / BM);   // (8, 64)
    sgemm_bias<<<ggrid, 256>>>(x, Wq, bq, pQ, MROWS, HID, HID);
    sgemm_bias<<<ggrid, 256>>>(x, Wk, bk, pK, MROWS, HID, HID);
    sgemm_bias<<<ggrid, 256>>>(x, Wv, bv, pV, MROWS, HID, HID);

    dim3 agrid(SEQ / QT, NHEAD, BATCH); // (16, 16, 8)
    flash_attn<<<agrid, QT>>>(pQ, pK, pV, pC);

    sgemm_bias<<<ggrid, 256>>>(pC, Wo, bo, out, MROWS, HID, HID);
}

// round 6
// speedup vs baseline: 1.6110x; 1.6110x over previous
#include <cuda_runtime.h>
#include <cuda_bf16.h>
#include <math.h>
#include <stdint.h>

// ---------------------------------------------------------------------------
// Problem constants
// ---------------------------------------------------------------------------
#define BATCH 8
#define SEQ   1024
#define HID   1024
#define NHEAD 16
#define HDIM  64
#define MROWS (BATCH * SEQ)   // 8192

typedef __nv_bfloat16  bf16;
typedef __nv_bfloat162 bf162;

// ---------------------------------------------------------------------------
// Scratch (device globals; no allocation allowed)
// ---------------------------------------------------------------------------
__device__ float g_Q[MROWS * HID];
__device__ float g_K[MROWS * HID];
__device__ float g_V[MROWS * HID];
__device__ float g_C[MROWS * HID];
__device__ bf16  g_xhi[MROWS * HID];
__device__ bf16  g_xlo[MROWS * HID];
__device__ bf16  g_chi[MROWS * HID];
__device__ bf16  g_clo[MROWS * HID];
__device__ bf16  g_wthi[HID * HID];   // transposed weight hi  [N,K]
__device__ bf16  g_wtlo[HID * HID];   // transposed weight lo  [N,K]

// ---------------------------------------------------------------------------
// Helpers
// ---------------------------------------------------------------------------
__device__ __forceinline__ uint32_t smem_u32(const void* p) {
    uint32_t a;
    asm("{ .reg .u64 t; cvta.to.shared.u64 t, %1; cvt.u32.u64 %0, t; }"
        : "=r"(a) : "l"(p));
    return a;
}

#define SW128(o) ((o) ^ (((o) >> 3) & 0x70))

__device__ __forceinline__ void cp16(uint32_t smem, const void* g) {
    asm volatile("cp.async.cg.shared.global [%0], [%1], 16;" :: "r"(smem), "l"(g));
}
#define CP_COMMIT()  asm volatile("cp.async.commit_group;" ::: "memory")
#define CP_WAIT1()   asm volatile("cp.async.wait_group 1;" ::: "memory")
#define CP_WAIT0()   asm volatile("cp.async.wait_group 0;" ::: "memory")

__device__ __forceinline__ void ldsm4(uint32_t* r, uint32_t addr) {
    asm volatile("ldmatrix.sync.aligned.m8n8.x4.shared.b16 {%0,%1,%2,%3}, [%4];"
        : "=r"(r[0]), "=r"(r[1]), "=r"(r[2]), "=r"(r[3]) : "r"(addr));
}
__device__ __forceinline__ void ldsm2(uint32_t* r, uint32_t addr) {
    asm volatile("ldmatrix.sync.aligned.m8n8.x2.shared.b16 {%0,%1}, [%2];"
        : "=r"(r[0]), "=r"(r[1]) : "r"(addr));
}
__device__ __forceinline__ void mma16816(float* c, const uint32_t* a, const uint32_t* b) {
    asm volatile("mma.sync.aligned.m16n8k16.row.col.f32.bf16.bf16.f32 "
        "{%0,%1,%2,%3}, {%4,%5,%6,%7}, {%8,%9}, {%0,%1,%2,%3};"
        : "+f"(c[0]), "+f"(c[1]), "+f"(c[2]), "+f"(c[3])
        : "r"(a[0]), "r"(a[1]), "r"(a[2]), "r"(a[3]), "r"(b[0]), "r"(b[1]));
}

// ---------------------------------------------------------------------------
// Split-convert kernels: fp32 -> (bf16 hi, bf16 lo) with lo = x - float(hi)
// ---------------------------------------------------------------------------
__global__ void convert_split(const float4* __restrict__ in,
                              bf162* __restrict__ hi2, bf162* __restrict__ lo2, int n4)
{
    for (int i = blockIdx.x * blockDim.x + threadIdx.x; i < n4; i += gridDim.x * blockDim.x) {
        float4 v = in[i];
        bf162 h01 = __floats2bfloat162_rn(v.x, v.y);
        bf162 h23 = __floats2bfloat162_rn(v.z, v.w);
        float2 f01 = __bfloat1622float2(h01);
        float2 f23 = __bfloat1622float2(h23);
        bf162 l01 = __floats2bfloat162_rn(v.x - f01.x, v.y - f01.y);
        bf162 l23 = __floats2bfloat162_rn(v.z - f23.x, v.w - f23.y);
        hi2[2 * i] = h01; hi2[2 * i + 1] = h23;
        lo2[2 * i] = l01; lo2[2 * i + 1] = l23;
    }
}

// Transpose + split: Wt[n*HID + k] = split(W[k*HID + n]). Block 32x8, tile 32x32.
__global__ void convert_wt(const float* __restrict__ W,
                           bf16* __restrict__ thi, bf16* __restrict__ tlo)
{
    __shared__ float t[32][33];
    int n0 = blockIdx.x * 32, k0 = blockIdx.y * 32;
    int tx = threadIdx.x, ty = threadIdx.y;
    #pragma unroll
    for (int r = 0; r < 32; r += 8)
        t[ty + r][tx] = W[(size_t)(k0 + ty + r) * HID + n0 + tx];
    __syncthreads();
    #pragma unroll
    for (int r = 0; r < 32; r += 8) {
        float v = t[tx][ty + r];
        bf16 h = __float2bfloat16(v);
        float l = v - __bfloat162float(h);
        size_t o = (size_t)(n0 + ty + r) * HID + k0 + tx;
        thi[o] = h;
        tlo[o] = __float2bfloat16(l);
    }
}

// ---------------------------------------------------------------------------
// mma.sync GEMM, 3-term bf16 split: C[M,N] = A @ W + bias  (fp32 in/out)
// A given as (Ahi, Alo) [M,K] bf16;  B given as (Bhi, Blo) transposed [N,K] bf16.
// CTA tile 128x64, K-chunk 32, 2-stage cp.async double buffer.
// STATIC 48KB shared memory (no cudaFuncSetAttribute, no dynamic smem).
// Each 128-byte smem row packs hi (bytes 0-63) and lo (bytes 64-127) for one
// matrix row's 32-element K-chunk; SW128 swizzle applies per row.
// 8 warps = 4(m) x 2(n); warp tile 32x32; mma.m16n8k16 bf16 -> fp32.
// ---------------------------------------------------------------------------
#define GKC        32
#define NCHUNK     (HID / GKC)       // 32
#define OFF_B      16384             // A: 128 rows * 128B; B: 64 rows * 128B
#define STAGE_BYTES 24576
#define GEMM_SMEM  (2 * STAGE_BYTES) // 49152 (static)

__device__ __forceinline__ void load_chunk(uint32_t sbase,
    const bf16* __restrict__ Ahi, const bf16* __restrict__ Alo,
    const bf16* __restrict__ Bhi, const bf16* __restrict__ Blo,
    int by, int bx, int k0, int tid)
{
    // A: 128 rows; per row 8x16B units (4 hi + 4 lo) = 1024 units -> 4/thread
    #pragma unroll
    for (int r = 0; r < 4; r++) {
        int u    = r * 256 + tid;
        int m    = u >> 3;
        int part = (u >> 2) & 1;          // 0 = hi, 1 = lo
        int seg  = u & 3;                 // 16B segment within 64B half
        uint32_t so = SW128((uint32_t)(m * 128 + part * 64 + seg * 16));
        const bf16* src = (part ? Alo : Ahi) + (size_t)(by * 128 + m) * HID + k0 + seg * 8;
        cp16(sbase + so, src);
    }
    // B: 64 rows; 512 units -> 2/thread
    #pragma unroll
    for (int r = 0; r < 2; r++) {
        int u    = r * 256 + tid;
        int n    = u >> 3;
        int part = (u >> 2) & 1;
        int seg  = u & 3;
        uint32_t so = SW128((uint32_t)(n * 128 + part * 64 + seg * 16));
        const bf16* src = (part ? Blo : Bhi) + (size_t)(bx * 64 + n) * HID + k0 + seg * 8;
        cp16(sbase + OFF_B + so, src);
    }
}

__global__ __launch_bounds__(256)
void gemm_bf16x3(const bf16* __restrict__ Ahi, const bf16* __restrict__ Alo,
                 const bf16* __restrict__ Bhi, const bf16* __restrict__ Blo,
                 const float* __restrict__ bias, float* __restrict__ C)
{
    __shared__ __align__(128) char smem[GEMM_SMEM];
    uint32_t sb = smem_u32(smem);
    const int tid  = threadIdx.x;
    const int lane = tid & 31;
    const int wid  = tid >> 5;
    const int bx = blockIdx.x, by = blockIdx.y;

    const int wm = (wid & 3) * 32;    // warp m offset
    const int wn = (wid >> 2) * 32;   // warp n offset (0 or 32)

    float c[2][4][4];
    #pragma unroll
    for (int mt = 0; mt < 2; mt++)
        #pragma unroll
        for (int nt = 0; nt < 4; nt++)
            #pragma unroll
            for (int i = 0; i < 4; i++) c[mt][nt][i] = 0.0f;

    // ldmatrix lane geometry
    const int a_r    = (lane & 7) + ((lane >> 3) & 1) * 8;
    const int a_kb16 = (lane >> 4) * 16;
    const int l16    = lane & 15;
    const int b_r    = l16 & 7;
    const int b_kb16 = (l16 >> 3) * 16;

    // Prologue: stage 0
    load_chunk(sb, Ahi, Alo, Bhi, Blo, by, bx, 0, tid);
    CP_COMMIT();

    for (int ch = 0; ch < NCHUNK; ch++) {
        const uint32_t sbase = sb + (ch & 1) * STAGE_BYTES;

        if (ch + 1 < NCHUNK) {
            load_chunk(sb + ((ch + 1) & 1) * STAGE_BYTES,
                       Ahi, Alo, Bhi, Blo, by, bx, (ch + 1) * GKC, tid);
            CP_COMMIT();
            CP_WAIT1();          // chunk ch resident, chunk ch+1 may be in flight
        } else {
            CP_WAIT0();          // final chunk resident
        }
        __syncthreads();

        const uint32_t ab = sbase;
        const uint32_t bb = sbase + OFF_B;

        #pragma unroll
        for (int ks = 0; ks < 2; ks++) {
            const int kb = ks * 32;   // byte offset of this k16 within the 64B half

            uint32_t Ah[2][4], Al[2][4];
            #pragma unroll
            for (int mt = 0; mt < 2; mt++) {
                int row = wm + mt * 16 + a_r;
                uint32_t colh = (uint32_t)((kb + a_kb16)      ^ ((row & 7) << 4));
                uint32_t coll = (uint32_t)((kb + a_kb16 + 64) ^ ((row & 7) << 4));
                ldsm4(Ah[mt], ab + (uint32_t)(row * 128) + colh);
                ldsm4(Al[mt], ab + (uint32_t)(row * 128) + coll);
            }

            #pragma unroll
            for (int nt = 0; nt < 4; nt++) {
                int nrow = wn + nt * 8 + b_r;
                uint32_t colh = (uint32_t)((kb + b_kb16)      ^ ((nrow & 7) << 4));
                uint32_t coll = (uint32_t)((kb + b_kb16 + 64) ^ ((nrow & 7) << 4));
                uint32_t Bh[2], Bl[2];
                ldsm2(Bh, bb + (uint32_t)(nrow * 128) + colh);
                ldsm2(Bl, bb + (uint32_t)(nrow * 128) + coll);
                mma16816(c[0][nt], Ah[0], Bh);
                mma16816(c[1][nt], Ah[1], Bh);
                mma16816(c[0][nt], Ah[0], Bl);
                mma16816(c[1][nt], Ah[1], Bl);
                mma16816(c[0][nt], Al[0], Bh);
                mma16816(c[1][nt], Al[1], Bh);
            }
        }

        __syncthreads();   // compute done before next iteration's load overwrites
    }

    // Epilogue: accumulators -> gmem (float2 stores), fused bias.
    const int crow0 = by * 128 + wm + (lane >> 2);
    const int ccol0 = bx * 64 + wn + (lane & 3) * 2;
    #pragma unroll
    for (int nt = 0; nt < 4; nt++) {
        float2 bb = *(const float2*)&bias[ccol0 + nt * 8];
        #pragma unroll
        for (int mt = 0; mt < 2; mt++) {
            #pragma unroll
            for (int h = 0; h < 2; h++) {
                int row = crow0 + mt * 16 + h * 8;
                float2 v;
                v.x = c[mt][nt][2 * h + 0] + bb.x;
                v.y = c[mt][nt][2 * h + 1] + bb.y;
                *(float2*)&C[(size_t)row * HID + ccol0 + nt * 8] = v;
            }
        }
    }
}

// ---------------------------------------------------------------------------
// Fused flash attention (exact round-1 version, proven pass):
// one thread = one query row, 64 threads/block.
// ---------------------------------------------------------------------------
#define QT 64
#define KT 64

__global__ __launch_bounds__(64)
void flash_attn(const float* __restrict__ Q,
                const float* __restrict__ K,
                const float* __restrict__ V,
                float* __restrict__ O)
{
    __shared__ float Ks[KT][HDIM];
    __shared__ float Vs[KT][HDIM];

    const int q0 = blockIdx.x * QT;
    const int h  = blockIdx.y;
    const int b  = blockIdx.z;
    const int t  = threadIdx.x;

    const float* qptr = Q + ((size_t)(b * SEQ + q0 + t)) * HID + h * HDIM;
    float q[HDIM];
    #pragma unroll
    for (int i = 0; i < HDIM / 4; i++)
        *(float4*)&q[i * 4] = *(const float4*)(qptr + i * 4);

    float o[HDIM];
    #pragma unroll
    for (int d = 0; d < HDIM; d++) o[d] = 0.0f;
    float m = -INFINITY;
    float l = 0.0f;

    for (int k0 = 0; k0 < SEQ; k0 += KT) {
        const float* kbase = K + ((size_t)(b * SEQ + k0)) * HID + h * HDIM;
        const float* vbase = V + ((size_t)(b * SEQ + k0)) * HID + h * HDIM;
        #pragma unroll
        for (int i = 0; i < 16; i++) {
            int idx = i * 64 + t;
            int row = idx >> 4;
            int c4  = (idx & 15) * 4;
            *(float4*)&Ks[row][c4] = *(const float4*)(kbase + (size_t)row * HID + c4);
            *(float4*)&Vs[row][c4] = *(const float4*)(vbase + (size_t)row * HID + c4);
        }
        __syncthreads();

        float s[KT];
        #pragma unroll 4
        for (int j = 0; j < KT; j++) {
            float a0 = 0.0f, a1 = 0.0f;
            #pragma unroll
            for (int d4 = 0; d4 < HDIM; d4 += 8) {
                float4 k0v = *(const float4*)&Ks[j][d4];
                float4 k1v = *(const float4*)&Ks[j][d4 + 4];
                a0 = fmaf(q[d4 + 0], k0v.x, a0);
                a0 = fmaf(q[d4 + 1], k0v.y, a0);
                a0 = fmaf(q[d4 + 2], k0v.z, a0);
                a0 = fmaf(q[d4 + 3], k0v.w, a0);
                a1 = fmaf(q[d4 + 4], k1v.x, a1);
                a1 = fmaf(q[d4 + 5], k1v.y, a1);
                a1 = fmaf(q[d4 + 6], k1v.z, a1);
                a1 = fmaf(q[d4 + 7], k1v.w, a1);
            }
            s[j] = (a0 + a1) * 0.125f;
        }

        float mt = m;
        #pragma unroll
        for (int j = 0; j < KT; j++) mt = fmaxf(mt, s[j]);
        float factor = __expf(m - mt);
        m = mt;
        float lsum = 0.0f;
        #pragma unroll
        for (int j = 0; j < KT; j++) {
            s[j] = __expf(s[j] - m);
            lsum += s[j];
        }
        l = l * factor + lsum;
        #pragma unroll
        for (int d = 0; d < HDIM; d++) o[d] *= factor;

        #pragma unroll 4
        for (int j = 0; j < KT; j++) {
            float p = s[j];
            #pragma unroll
            for (int d4 = 0; d4 < HDIM; d4 += 4) {
                float4 vv = *(const float4*)&Vs[j][d4];
                o[d4 + 0] = fmaf(p, vv.x, o[d4 + 0]);
                o[d4 + 1] = fmaf(p, vv.y, o[d4 + 1]);
                o[d4 + 2] = fmaf(p, vv.z, o[d4 + 2]);
                o[d4 + 3] = fmaf(p, vv.w, o[d4 + 3]);
            }
        }
        __syncthreads();
    }

    const float inv = 1.0f / l;
    float* optr = O + ((size_t)(b * SEQ + q0 + t)) * HID + h * HDIM;
    #pragma unroll
    for (int i = 0; i < HDIM / 4; i++) {
        float4 r;
        r.x = o[i * 4 + 0] * inv;
        r.y = o[i * 4 + 1] * inv;
        r.z = o[i * 4 + 2] * inv;
        r.w = o[i * 4 + 3] * inv;
        *(float4*)(optr + i * 4) = r;
    }
}

// ---------------------------------------------------------------------------
// Launch (no cudaFuncSetAttribute, no dynamic smem)
// ---------------------------------------------------------------------------
extern "C" void kernel_launch(void* const* d_in, const int* in_sizes, int n_in,
                              void* d_out, int out_size)
{
    const float* x  = (const float*)d_in[0];
    const float* Wq = (const float*)d_in[1];
    const float* bq = (const float*)d_in[2];
    const float* Wk = (const float*)d_in[3];
    const float* bk = (const float*)d_in[4];
    const float* Wv = (const float*)d_in[5];
    const float* bv = (const float*)d_in[6];
    const float* Wo = (const float*)d_in[7];
    const float* bo = (const float*)d_in[8];
    float* out = (float*)d_out;

    float *pQ, *pK, *pV, *pC;
    bf16 *xhi, *xlo, *chi, *clo, *wthi, *wtlo;
    cudaGetSymbolAddress((void**)&pQ, g_Q);
    cudaGetSymbolAddress((void**)&pK, g_K);
    cudaGetSymbolAddress((void**)&pV, g_V);
    cudaGetSymbolAddress((void**)&pC, g_C);
    cudaGetSymbolAddress((void**)&xhi, g_xhi);
    cudaGetSymbolAddress((void**)&xlo, g_xlo);
    cudaGetSymbolAddress((void**)&chi, g_chi);
    cudaGetSymbolAddress((void**)&clo, g_clo);
    cudaGetSymbolAddress((void**)&wthi, g_wthi);
    cudaGetSymbolAddress((void**)&wtlo, g_wtlo);

    const int n4x = MROWS * HID / 4;
    dim3 wtg(HID / 32, HID / 32);
    dim3 wtb(32, 8);
    dim3 ggrid(HID / 64, MROWS / 128);   // (16, 64)

    convert_split<<<2048, 256>>>((const float4*)x, (bf162*)xhi, (bf162*)xlo, n4x);

    convert_wt<<<wtg, wtb>>>(Wq, wthi, wtlo);
    gemm_bf16x3<<<ggrid, 256>>>(xhi, xlo, wthi, wtlo, bq, pQ);
    convert_wt<<<wtg, wtb>>>(Wk, wthi, wtlo);
    gemm_bf16x3<<<ggrid, 256>>>(xhi, xlo, wthi, wtlo, bk, pK);
    convert_wt<<<wtg, wtb>>>(Wv, wthi, wtlo);
    gemm_bf16x3<<<ggrid, 256>>>(xhi, xlo, wthi, wtlo, bv, pV);

    dim3 agrid(SEQ / QT, NHEAD, BATCH);   // (16, 16, 8)
    flash_attn<<<agrid, QT>>>(pQ, pK, pV, pC);

    convert_split<<<2048, 256>>>((const float4*)pC, (bf162*)chi, (bf162*)clo, n4x);
    convert_wt<<<wtg, wtb>>>(Wo, wthi, wtlo);
    gemm_bf16x3<<<ggrid, 256>>>(chi, clo, wthi, wtlo, bo, out);
}

// round 7
// speedup vs baseline: 3.4411x; 2.1359x over previous
#include <cuda_runtime.h>
#include <cuda_bf16.h>
#include <math.h>
#include <stdint.h>

// ---------------------------------------------------------------------------
// Problem constants
// ---------------------------------------------------------------------------
#define BATCH 8
#define SEQ   1024
#define HID   1024
#define NHEAD 16
#define HDIM  64
#define MROWS (BATCH * SEQ)   // 8192

typedef __nv_bfloat16  bf16;
typedef __nv_bfloat162 bf162;

// ---------------------------------------------------------------------------
// Scratch (device globals; no allocation allowed)
// ---------------------------------------------------------------------------
__device__ bf16  g_xhi[MROWS * HID];
__device__ bf16  g_xlo[MROWS * HID];
__device__ bf16  g_qhi[MROWS * HID];
__device__ bf16  g_qlo[MROWS * HID];
__device__ bf16  g_khi[MROWS * HID];
__device__ bf16  g_klo[MROWS * HID];
__device__ bf16  g_vhi[MROWS * HID];
__device__ bf16  g_vlo[MROWS * HID];
__device__ bf16  g_chi[MROWS * HID];
__device__ bf16  g_clo[MROWS * HID];
__device__ bf16  g_wthi[HID * HID];   // transposed weight hi  [N,K]
__device__ bf16  g_wtlo[HID * HID];   // transposed weight lo  [N,K]

// ---------------------------------------------------------------------------
// Helpers
// ---------------------------------------------------------------------------
__device__ __forceinline__ uint32_t smem_u32(const void* p) {
    uint32_t a;
    asm("{ .reg .u64 t; cvta.to.shared.u64 t, %1; cvt.u32.u64 %0, t; }"
        : "=r"(a) : "l"(p));
    return a;
}

#define SW128(o) ((o) ^ (((o) >> 3) & 0x70))

__device__ __forceinline__ void cp16(uint32_t smem, const void* g) {
    asm volatile("cp.async.cg.shared.global [%0], [%1], 16;" :: "r"(smem), "l"(g));
}
#define CP_COMMIT()  asm volatile("cp.async.commit_group;" ::: "memory")
#define CP_WAIT1()   asm volatile("cp.async.wait_group 1;" ::: "memory")
#define CP_WAIT0()   asm volatile("cp.async.wait_group 0;" ::: "memory")

__device__ __forceinline__ void ldsm4(uint32_t* r, uint32_t addr) {
    asm volatile("ldmatrix.sync.aligned.m8n8.x4.shared.b16 {%0,%1,%2,%3}, [%4];"
        : "=r"(r[0]), "=r"(r[1]), "=r"(r[2]), "=r"(r[3]) : "r"(addr));
}
__device__ __forceinline__ void ldsm2(uint32_t* r, uint32_t addr) {
    asm volatile("ldmatrix.sync.aligned.m8n8.x2.shared.b16 {%0,%1}, [%2];"
        : "=r"(r[0]), "=r"(r[1]) : "r"(addr));
}
__device__ __forceinline__ void ldsm4t(uint32_t* r, uint32_t addr) {
    asm volatile("ldmatrix.sync.aligned.m8n8.x4.trans.shared.b16 {%0,%1,%2,%3}, [%4];"
        : "=r"(r[0]), "=r"(r[1]), "=r"(r[2]), "=r"(r[3]) : "r"(addr));
}
__device__ __forceinline__ void mma16816(float* c, const uint32_t* a, const uint32_t* b) {
    asm volatile("mma.sync.aligned.m16n8k16.row.col.f32.bf16.bf16.f32 "
        "{%0,%1,%2,%3}, {%4,%5,%6,%7}, {%8,%9}, {%0,%1,%2,%3};"
        : "+f"(c[0]), "+f"(c[1]), "+f"(c[2]), "+f"(c[3])
        : "r"(a[0]), "r"(a[1]), "r"(a[2]), "r"(a[3]), "r"(b[0]), "r"(b[1]));
}

// ---------------------------------------------------------------------------
// Split-convert kernels: fp32 -> (bf16 hi, bf16 lo) with lo = x - float(hi)
// ---------------------------------------------------------------------------
__global__ void convert_split(const float4* __restrict__ in,
                              bf162* __restrict__ hi2, bf162* __restrict__ lo2, int n4)
{
    for (int i = blockIdx.x * blockDim.x + threadIdx.x; i < n4; i += gridDim.x * blockDim.x) {
        float4 v = in[i];
        bf162 h01 = __floats2bfloat162_rn(v.x, v.y);
        bf162 h23 = __floats2bfloat162_rn(v.z, v.w);
        float2 f01 = __bfloat1622float2(h01);
        float2 f23 = __bfloat1622float2(h23);
        bf162 l01 = __floats2bfloat162_rn(v.x - f01.x, v.y - f01.y);
        bf162 l23 = __floats2bfloat162_rn(v.z - f23.x, v.w - f23.y);
        hi2[2 * i] = h01; hi2[2 * i + 1] = h23;
        lo2[2 * i] = l01; lo2[2 * i + 1] = l23;
    }
}

// Transpose + split: Wt[n*HID + k] = split(W[k*HID + n]). Block 32x8, tile 32x32.
__global__ void convert_wt(const float* __restrict__ W,
                           bf16* __restrict__ thi, bf16* __restrict__ tlo)
{
    __shared__ float t[32][33];
    int n0 = blockIdx.x * 32, k0 = blockIdx.y * 32;
    int tx = threadIdx.x, ty = threadIdx.y;
    #pragma unroll
    for (int r = 0; r < 32; r += 8)
        t[ty + r][tx] = W[(size_t)(k0 + ty + r) * HID + n0 + tx];
    __syncthreads();
    #pragma unroll
    for (int r = 0; r < 32; r += 8) {
        float v = t[tx][ty + r];
        bf16 h = __float2bfloat16(v);
        float l = v - __bfloat162float(h);
        size_t o = (size_t)(n0 + ty + r) * HID + k0 + tx;
        thi[o] = h;
        tlo[o] = __float2bfloat16(l);
    }
}

// ---------------------------------------------------------------------------
// mma.sync GEMM, 3-term bf16 split (unchanged core from round 6).
// New epilogue: optional fp32 output Cf, optional bf16 hi/lo split outputs,
// uniform scale applied to (acc + bias)  (0.125 for Q — exact power of two).
// ---------------------------------------------------------------------------
#define GKC        32
#define NCHUNK     (HID / GKC)       // 32
#define OFF_B      16384
#define STAGE_BYTES 24576
#define GEMM_SMEM  (2 * STAGE_BYTES) // 49152 (static)

__device__ __forceinline__ void load_chunk(uint32_t sbase,
    const bf16* __restrict__ Ahi, const bf16* __restrict__ Alo,
    const bf16* __restrict__ Bhi, const bf16* __restrict__ Blo,
    int by, int bx, int k0, int tid)
{
    #pragma unroll
    for (int r = 0; r < 4; r++) {
        int u    = r * 256 + tid;
        int m    = u >> 3;
        int part = (u >> 2) & 1;
        int seg  = u & 3;
        uint32_t so = SW128((uint32_t)(m * 128 + part * 64 + seg * 16));
        const bf16* src = (part ? Alo : Ahi) + (size_t)(by * 128 + m) * HID + k0 + seg * 8;
        cp16(sbase + so, src);
    }
    #pragma unroll
    for (int r = 0; r < 2; r++) {
        int u    = r * 256 + tid;
        int n    = u >> 3;
        int part = (u >> 2) & 1;
        int seg  = u & 3;
        uint32_t so = SW128((uint32_t)(n * 128 + part * 64 + seg * 16));
        const bf16* src = (part ? Blo : Bhi) + (size_t)(bx * 64 + n) * HID + k0 + seg * 8;
        cp16(sbase + OFF_B + so, src);
    }
}

__global__ __launch_bounds__(256)
void gemm_bf16x3(const bf16* __restrict__ Ahi, const bf16* __restrict__ Alo,
                 const bf16* __restrict__ Bhi, const bf16* __restrict__ Blo,
                 const float* __restrict__ bias,
                 float* __restrict__ Cf,
                 bf16* __restrict__ Ohi, bf16* __restrict__ Olo,
                 float scale)
{
    __shared__ __align__(128) char smem[GEMM_SMEM];
    uint32_t sb = smem_u32(smem);
    const int tid  = threadIdx.x;
    const int lane = tid & 31;
    const int wid  = tid >> 5;
    const int bx = blockIdx.x, by = blockIdx.y;

    const int wm = (wid & 3) * 32;
    const int wn = (wid >> 2) * 32;

    float c[2][4][4];
    #pragma unroll
    for (int mt = 0; mt < 2; mt++)
        #pragma unroll
        for (int nt = 0; nt < 4; nt++)
            #pragma unroll
            for (int i = 0; i < 4; i++) c[mt][nt][i] = 0.0f;

    const int a_r    = (lane & 7) + ((lane >> 3) & 1) * 8;
    const int a_kb16 = (lane >> 4) * 16;
    const int l16    = lane & 15;
    const int b_r    = l16 & 7;
    const int b_kb16 = (l16 >> 3) * 16;

    load_chunk(sb, Ahi, Alo, Bhi, Blo, by, bx, 0, tid);
    CP_COMMIT();

    for (int ch = 0; ch < NCHUNK; ch++) {
        const uint32_t sbase = sb + (ch & 1) * STAGE_BYTES;

        if (ch + 1 < NCHUNK) {
            load_chunk(sb + ((ch + 1) & 1) * STAGE_BYTES,
                       Ahi, Alo, Bhi, Blo, by, bx, (ch + 1) * GKC, tid);
            CP_COMMIT();
            CP_WAIT1();
        } else {
            CP_WAIT0();
        }
        __syncthreads();

        const uint32_t ab = sbase;
        const uint32_t bb = sbase + OFF_B;

        #pragma unroll
        for (int ks = 0; ks < 2; ks++) {
            const int kb = ks * 32;

            uint32_t Ah[2][4], Al[2][4];
            #pragma unroll
            for (int mt = 0; mt < 2; mt++) {
                int row = wm + mt * 16 + a_r;
                uint32_t colh = (uint32_t)((kb + a_kb16)      ^ ((row & 7) << 4));
                uint32_t coll = (uint32_t)((kb + a_kb16 + 64) ^ ((row & 7) << 4));
                ldsm4(Ah[mt], ab + (uint32_t)(row * 128) + colh);
                ldsm4(Al[mt], ab + (uint32_t)(row * 128) + coll);
            }

            #pragma unroll
            for (int nt = 0; nt < 4; nt++) {
                int nrow = wn + nt * 8 + b_r;
                uint32_t colh = (uint32_t)((kb + b_kb16)      ^ ((nrow & 7) << 4));
                uint32_t coll = (uint32_t)((kb + b_kb16 + 64) ^ ((nrow & 7) << 4));
                uint32_t Bh[2], Bl[2];
                ldsm2(Bh, bb + (uint32_t)(nrow * 128) + colh);
                ldsm2(Bl, bb + (uint32_t)(nrow * 128) + coll);
                mma16816(c[0][nt], Ah[0], Bh);
                mma16816(c[1][nt], Ah[1], Bh);
                mma16816(c[0][nt], Ah[0], Bl);
                mma16816(c[1][nt], Ah[1], Bl);
                mma16816(c[0][nt], Al[0], Bh);
                mma16816(c[1][nt], Al[1], Bh);
            }
        }

        __syncthreads();
    }

    // Epilogue
    const int crow0 = by * 128 + wm + (lane >> 2);
    const int ccol0 = bx * 64 + wn + (lane & 3) * 2;
    #pragma unroll
    for (int nt = 0; nt < 4; nt++) {
        float2 bb = *(const float2*)&bias[ccol0 + nt * 8];
        #pragma unroll
        for (int mt = 0; mt < 2; mt++) {
            #pragma unroll
            for (int h = 0; h < 2; h++) {
                int row = crow0 + mt * 16 + h * 8;
                float vx = (c[mt][nt][2 * h + 0] + bb.x) * scale;
                float vy = (c[mt][nt][2 * h + 1] + bb.y) * scale;
                size_t idx = (size_t)row * HID + ccol0 + nt * 8;
                if (Cf) {
                    float2 v; v.x = vx; v.y = vy;
                    *(float2*)&Cf[idx] = v;
                }
                if (Ohi) {
                    bf162 hi2 = __floats2bfloat162_rn(vx, vy);
                    float2 hf = __bfloat1622float2(hi2);
                    bf162 lo2 = __floats2bfloat162_rn(vx - hf.x, vy - hf.y);
                    *(bf162*)&Ohi[idx] = hi2;
                    *(bf162*)&Olo[idx] = lo2;
                }
            }
        }
    }
}

// ---------------------------------------------------------------------------
// Tensor-core flash attention with bf16 split.
// Per CTA: 64 queries x one (b,h). 4 warps, each owns 16 query rows.
// S = Qhi*Khi + Qhi*Klo + Qlo*Khi  (Q pre-scaled by 0.125, exact)
// O += Phi*Vhi + Phi*Vlo + Plo*Vhi
// Static smem 48KB: Q(hi,lo) 16K persistent + K(hi,lo) 16K + V(hi,lo) 16K.
// Output: bf16 hi/lo split of attention output (feeds O-projection GEMM).
// ---------------------------------------------------------------------------
#define SQ_HI 0
#define SQ_LO 8192
#define SK_HI 16384
#define SK_LO 24576
#define SV_HI 32768
#define SV_LO 40960
#define ATT_SMEM 49152

__global__ __launch_bounds__(128)
void flash_attn_mma(const bf16* __restrict__ Qhi, const bf16* __restrict__ Qlo,
                    const bf16* __restrict__ Khi, const bf16* __restrict__ Klo,
                    const bf16* __restrict__ Vhi, const bf16* __restrict__ Vlo,
                    bf16* __restrict__ Chi, bf16* __restrict__ Clo)
{
    __shared__ __align__(128) char smem[ATT_SMEM];
    uint32_t sb = smem_u32(smem);
    const int tid  = threadIdx.x;
    const int lane = tid & 31;
    const int wid  = tid >> 5;
    const int q0 = blockIdx.x * 64;
    const int h  = blockIdx.y;
    const int b  = blockIdx.z;

    const size_t qg  = ((size_t)(b * SEQ + q0)) * HID + h * HDIM;
    const size_t kvg = ((size_t)(b * SEQ)) * HID + h * HDIM;

    // Load Q tile (64 rows x 64 bf16, hi & lo)
    #pragma unroll
    for (int r = 0; r < 4; r++) {
        int u = r * 128 + tid;
        int row = u >> 3, seg = u & 7;
        uint32_t so = SW128((uint32_t)(row * 128 + seg * 16));
        cp16(sb + SQ_HI + so, Qhi + qg + (size_t)row * HID + seg * 8);
        cp16(sb + SQ_LO + so, Qlo + qg + (size_t)row * HID + seg * 8);
    }
    CP_COMMIT();

    const int wm = wid * 16;
    const int a_r    = (lane & 7) + ((lane >> 3) & 1) * 8;
    const int a_kb16 = (lane >> 4) * 16;
    const int b_r    = lane & 7;                 // with x4 pairing below
    const int b_kb16 = ((lane >> 3) & 1) * 16;

    CP_WAIT0();
    __syncthreads();

    // Cache Q A-fragments (4 k16-chunks, hi & lo)
    uint32_t qh[4][4], ql[4][4];
    #pragma unroll
    for (int kc = 0; kc < 4; kc++) {
        int row = wm + a_r;
        uint32_t col = (uint32_t)((kc * 32 + a_kb16) ^ ((row & 7) << 4));
        ldsm4(qh[kc], sb + SQ_HI + (uint32_t)(row * 128) + col);
        ldsm4(ql[kc], sb + SQ_LO + (uint32_t)(row * 128) + col);
    }

    float m0 = -INFINITY, m1 = -INFINITY, l0 = 0.0f, l1 = 0.0f;
    float o[8][4];
    #pragma unroll
    for (int nt = 0; nt < 8; nt++)
        #pragma unroll
        for (int i = 0; i < 4; i++) o[nt][i] = 0.0f;

    for (int kt = 0; kt < SEQ / 64; kt++) {
        // Load K/V tiles (single-buffered)
        const size_t kvb = kvg + (size_t)(kt * 64) * HID;
        #pragma unroll
        for (int r = 0; r < 4; r++) {
            int u = r * 128 + tid;
            int row = u >> 3, seg = u & 7;
            uint32_t so = SW128((uint32_t)(row * 128 + seg * 16));
            const size_t g = kvb + (size_t)row * HID + seg * 8;
            cp16(sb + SK_HI + so, Khi + g);
            cp16(sb + SK_LO + so, Klo + g);
            cp16(sb + SV_HI + so, Vhi + g);
            cp16(sb + SV_LO + so, Vlo + g);
        }
        CP_COMMIT();
        CP_WAIT0();
        __syncthreads();

        // ---- S = Q @ K^T (3 split terms) ----
        float s[8][4];
        #pragma unroll
        for (int nt = 0; nt < 8; nt++)
            #pragma unroll
            for (int i = 0; i < 4; i++) s[nt][i] = 0.0f;

        #pragma unroll
        for (int kc = 0; kc < 4; kc++) {
            #pragma unroll
            for (int ntp = 0; ntp < 4; ntp++) {       // pairs of key n-tiles
                int nrow = ntp * 16 + ((lane >> 4) & 1) * 8 + b_r;
                uint32_t col = (uint32_t)((kc * 32 + b_kb16) ^ ((nrow & 7) << 4));
                uint32_t kh[4], kl[4];
                ldsm4(kh, sb + SK_HI + (uint32_t)(nrow * 128) + col);
                ldsm4(kl, sb + SK_LO + (uint32_t)(nrow * 128) + col);
                mma16816(s[2 * ntp],     qh[kc], kh);
                mma16816(s[2 * ntp],     qh[kc], kl);
                mma16816(s[2 * ntp],     ql[kc], kh);
                mma16816(s[2 * ntp + 1], qh[kc], kh + 2);
                mma16816(s[2 * ntp + 1], qh[kc], kl + 2);
                mma16816(s[2 * ntp + 1], ql[kc], kh + 2);
            }
        }

        // ---- Online softmax (rows r=lane>>2 and r+8) ----
        float rmax0 = -INFINITY, rmax1 = -INFINITY;
        #pragma unroll
        for (int nt = 0; nt < 8; nt++) {
            rmax0 = fmaxf(rmax0, fmaxf(s[nt][0], s[nt][1]));
            rmax1 = fmaxf(rmax1, fmaxf(s[nt][2], s[nt][3]));
        }
        rmax0 = fmaxf(rmax0, __shfl_xor_sync(0xffffffffu, rmax0, 1));
        rmax0 = fmaxf(rmax0, __shfl_xor_sync(0xffffffffu, rmax0, 2));
        rmax1 = fmaxf(rmax1, __shfl_xor_sync(0xffffffffu, rmax1, 1));
        rmax1 = fmaxf(rmax1, __shfl_xor_sync(0xffffffffu, rmax1, 2));

        float mt0 = fmaxf(m0, rmax0), mt1 = fmaxf(m1, rmax1);
        float f0 = __expf(m0 - mt0),  f1 = __expf(m1 - mt1);
        m0 = mt0; m1 = mt1;

        float ls0 = 0.0f, ls1 = 0.0f;
        #pragma unroll
        for (int nt = 0; nt < 8; nt++) {
            s[nt][0] = __expf(s[nt][0] - m0);
            s[nt][1] = __expf(s[nt][1] - m0);
            s[nt][2] = __expf(s[nt][2] - m1);
            s[nt][3] = __expf(s[nt][3] - m1);
            ls0 += s[nt][0] + s[nt][1];
            ls1 += s[nt][2] + s[nt][3];
        }
        ls0 += __shfl_xor_sync(0xffffffffu, ls0, 1);
        ls0 += __shfl_xor_sync(0xffffffffu, ls0, 2);
        ls1 += __shfl_xor_sync(0xffffffffu, ls1, 1);
        ls1 += __shfl_xor_sync(0xffffffffu, ls1, 2);
        l0 = l0 * f0 + ls0;
        l1 = l1 * f1 + ls1;

        #pragma unroll
        for (int nt = 0; nt < 8; nt++) {
            o[nt][0] *= f0; o[nt][1] *= f0;
            o[nt][2] *= f1; o[nt][3] *= f1;
        }

        // ---- Pack P into A-fragments (hi + lo split) ----
        uint32_t phi[4][4], plo[4][4];
        #pragma unroll
        for (int kj = 0; kj < 4; kj++) {
            #pragma unroll
            for (int half = 0; half < 2; half++) {      // tiles 2kj, 2kj+1
                int t = 2 * kj + half;
                bf162 h0 = __floats2bfloat162_rn(s[t][0], s[t][1]);
                float2 hf0 = __bfloat1622float2(h0);
                bf162 lo0 = __floats2bfloat162_rn(s[t][0] - hf0.x, s[t][1] - hf0.y);
                bf162 h1 = __floats2bfloat162_rn(s[t][2], s[t][3]);
                float2 hf1 = __bfloat1622float2(h1);
                bf162 lo1 = __floats2bfloat162_rn(s[t][2] - hf1.x, s[t][3] - hf1.y);
                phi[kj][2 * half + 0] = *(uint32_t*)&h0;
                phi[kj][2 * half + 1] = *(uint32_t*)&h1;
                plo[kj][2 * half + 0] = *(uint32_t*)&lo0;
                plo[kj][2 * half + 1] = *(uint32_t*)&lo1;
            }
        }
        // Fix ordering: a-frag = {row, row+8 @k, row @k+8, row+8 @k+8}
        // phi[kj] currently {t0row, t0row8, t1row, t1row8} which is exactly
        // {a0, a1, a2, a3} — correct as built.

        // ---- O += P @ V (3 split terms), V via ldmatrix.trans ----
        #pragma unroll
        for (int kj = 0; kj < 4; kj++) {
            #pragma unroll
            for (int ntv = 0; ntv < 4; ntv++) {        // 16 hdim cols per step
                uint32_t voff = SW128((uint32_t)((kj * 16 + (lane & 15)) * 128 +
                                                 (ntv * 16 + 8 * (lane >> 4)) * 2));
                uint32_t vh[4], vl[4];
                ldsm4t(vh, sb + SV_HI + voff);
                ldsm4t(vl, sb + SV_LO + voff);
                mma16816(o[2 * ntv],     phi[kj], vh);
                mma16816(o[2 * ntv],     phi[kj], vl);
                mma16816(o[2 * ntv],     plo[kj], vh);
                mma16816(o[2 * ntv + 1], phi[kj], vh + 2);
                mma16816(o[2 * ntv + 1], phi[kj], vl + 2);
                mma16816(o[2 * ntv + 1], plo[kj], vh + 2);
            }
        }

        __syncthreads();   // compute done before next tile's loads overwrite
    }

    // ---- Finalize: divide by l, split to bf16 hi/lo, store ----
    const float inv0 = 1.0f / l0, inv1 = 1.0f / l1;
    const int row0 = q0 + wm + (lane >> 2);
    const int colb = (lane & 3) * 2;
    #pragma unroll
    for (int nt = 0; nt < 8; nt++) {
        {
            float vx = o[nt][0] * inv0, vy = o[nt][1] * inv0;
            size_t idx = ((size_t)(b * SEQ + row0)) * HID + h * HDIM + nt * 8 + colb;
            bf162 hi2 = __floats2bfloat162_rn(vx, vy);
            float2 hf = __bfloat1622float2(hi2);
            bf162 lo2 = __floats2bfloat162_rn(vx - hf.x, vy - hf.y);
            *(bf162*)&Chi[idx] = hi2;
            *(bf162*)&Clo[idx] = lo2;
        }
        {
            float vx = o[nt][2] * inv1, vy = o[nt][3] * inv1;
            size_t idx = ((size_t)(b * SEQ + row0 + 8)) * HID + h * HDIM + nt * 8 + colb;
            bf162 hi2 = __floats2bfloat162_rn(vx, vy);
            float2 hf = __bfloat1622float2(hi2);
            bf162 lo2 = __floats2bfloat162_rn(vx - hf.x, vy - hf.y);
            *(bf162*)&Chi[idx] = hi2;
            *(bf162*)&Clo[idx] = lo2;
        }
    }
}

// ---------------------------------------------------------------------------
// Launch (no cudaFuncSetAttribute, no dynamic smem)
// ---------------------------------------------------------------------------
extern "C" void kernel_launch(void* const* d_in, const int* in_sizes, int n_in,
                              void* d_out, int out_size)
{
    const float* x  = (const float*)d_in[0];
    const float* Wq = (const float*)d_in[1];
    const float* bq = (const float*)d_in[2];
    const float* Wk = (const float*)d_in[3];
    const float* bk = (const float*)d_in[4];
    const float* Wv = (const float*)d_in[5];
    const float* bv = (const float*)d_in[6];
    const float* Wo = (const float*)d_in[7];
    const float* bo = (const float*)d_in[8];
    float* out = (float*)d_out;

    bf16 *xhi, *xlo, *qhi, *qlo, *khi, *klo, *vhi, *vlo, *chi, *clo, *wthi, *wtlo;
    cudaGetSymbolAddress((void**)&xhi, g_xhi);
    cudaGetSymbolAddress((void**)&xlo, g_xlo);
    cudaGetSymbolAddress((void**)&qhi, g_qhi);
    cudaGetSymbolAddress((void**)&qlo, g_qlo);
    cudaGetSymbolAddress((void**)&khi, g_khi);
    cudaGetSymbolAddress((void**)&klo, g_klo);
    cudaGetSymbolAddress((void**)&vhi, g_vhi);
    cudaGetSymbolAddress((void**)&vlo, g_vlo);
    cudaGetSymbolAddress((void**)&chi, g_chi);
    cudaGetSymbolAddress((void**)&clo, g_clo);
    cudaGetSymbolAddress((void**)&wthi, g_wthi);
    cudaGetSymbolAddress((void**)&wtlo, g_wtlo);

    const int n4x = MROWS * HID / 4;
    dim3 wtg(HID / 32, HID / 32);
    dim3 wtb(32, 8);
    dim3 ggrid(HID / 64, MROWS / 128);   // (16, 64)

    convert_split<<<2048, 256>>>((const float4*)x, (bf162*)xhi, (bf162*)xlo, n4x);

    convert_wt<<<wtg, wtb>>>(Wq, wthi, wtlo);
    gemm_bf16x3<<<ggrid, 256>>>(xhi, xlo, wthi, wtlo, bq, nullptr, qhi, qlo, 0.125f);
    convert_wt<<<wtg, wtb>>>(Wk, wthi, wtlo);
    gemm_bf16x3<<<ggrid, 256>>>(xhi, xlo, wthi, wtlo, bk, nullptr, khi, klo, 1.0f);
    convert_wt<<<wtg, wtb>>>(Wv, wthi, wtlo);
    gemm_bf16x3<<<ggrid, 256>>>(xhi, xlo, wthi, wtlo, bv, nullptr, vhi, vlo, 1.0f);

    dim3 agrid(SEQ / 64, NHEAD, BATCH);   // (16, 16, 8)
    flash_attn_mma<<<agrid, 128>>>(qhi, qlo, khi, klo, vhi, vlo, chi, clo);

    convert_wt<<<wtg, wtb>>>(Wo, wthi, wtlo);
    gemm_bf16x3<<<ggrid, 256>>>(chi, clo, wthi, wtlo, bo, out, nullptr, nullptr, 1.0f);
}

// round 8
// speedup vs baseline: 3.5039x; 1.0183x over previous
#include <cuda_runtime.h>
#include <cuda_bf16.h>
#include <math.h>
#include <stdint.h>

// ---------------------------------------------------------------------------
// Problem constants
// ---------------------------------------------------------------------------
#define BATCH 8
#define SEQ   1024
#define HID   1024
#define NHEAD 16
#define HDIM  64
#define MROWS (BATCH * SEQ)   // 8192

typedef __nv_bfloat16  bf16;
typedef __nv_bfloat162 bf162;

// ---------------------------------------------------------------------------
// Scratch (device globals; no allocation allowed)
// ---------------------------------------------------------------------------
__device__ bf16  g_xhi[MROWS * HID];
__device__ bf16  g_xlo[MROWS * HID];
__device__ bf16  g_qhi[MROWS * HID];
__device__ bf16  g_qlo[MROWS * HID];
__device__ bf16  g_khi[MROWS * HID];
__device__ bf16  g_klo[MROWS * HID];
__device__ bf16  g_vhi[MROWS * HID];
__device__ bf16  g_vlo[MROWS * HID];
__device__ bf16  g_chi[MROWS * HID];
__device__ bf16  g_clo[MROWS * HID];
__device__ bf16  g_wt4hi[4 * HID * HID];   // transposed weights hi [N,K], 4 panels
__device__ bf16  g_wt4lo[4 * HID * HID];   // transposed weights lo

// ---------------------------------------------------------------------------
// Helpers
// ---------------------------------------------------------------------------
__device__ __forceinline__ uint32_t smem_u32(const void* p) {
    uint32_t a;
    asm("{ .reg .u64 t; cvta.to.shared.u64 t, %1; cvt.u32.u64 %0, t; }"
        : "=r"(a) : "l"(p));
    return a;
}

#define SW128(o) ((o) ^ (((o) >> 3) & 0x70))

__device__ __forceinline__ void cp16(uint32_t smem, const void* g) {
    asm volatile("cp.async.cg.shared.global [%0], [%1], 16;" :: "r"(smem), "l"(g));
}
#define CP_COMMIT()  asm volatile("cp.async.commit_group;" ::: "memory")
#define CP_WAIT1()   asm volatile("cp.async.wait_group 1;" ::: "memory")
#define CP_WAIT0()   asm volatile("cp.async.wait_group 0;" ::: "memory")

__device__ __forceinline__ void ldsm4(uint32_t* r, uint32_t addr) {
    asm volatile("ldmatrix.sync.aligned.m8n8.x4.shared.b16 {%0,%1,%2,%3}, [%4];"
        : "=r"(r[0]), "=r"(r[1]), "=r"(r[2]), "=r"(r[3]) : "r"(addr));
}
__device__ __forceinline__ void ldsm2(uint32_t* r, uint32_t addr) {
    asm volatile("ldmatrix.sync.aligned.m8n8.x2.shared.b16 {%0,%1}, [%2];"
        : "=r"(r[0]), "=r"(r[1]) : "r"(addr));
}
__device__ __forceinline__ void ldsm4t(uint32_t* r, uint32_t addr) {
    asm volatile("ldmatrix.sync.aligned.m8n8.x4.trans.shared.b16 {%0,%1,%2,%3}, [%4];"
        : "=r"(r[0]), "=r"(r[1]), "=r"(r[2]), "=r"(r[3]) : "r"(addr));
}
__device__ __forceinline__ void mma16816(float* c, const uint32_t* a, const uint32_t* b) {
    asm volatile("mma.sync.aligned.m16n8k16.row.col.f32.bf16.bf16.f32 "
        "{%0,%1,%2,%3}, {%4,%5,%6,%7}, {%8,%9}, {%0,%1,%2,%3};"
        : "+f"(c[0]), "+f"(c[1]), "+f"(c[2]), "+f"(c[3])
        : "r"(a[0]), "r"(a[1]), "r"(a[2]), "r"(a[3]), "r"(b[0]), "r"(b[1]));
}

// ---------------------------------------------------------------------------
// Split-convert: fp32 -> (bf16 hi, bf16 lo) with lo = x - float(hi)
// ---------------------------------------------------------------------------
__global__ void convert_split(const float4* __restrict__ in,
                              bf162* __restrict__ hi2, bf162* __restrict__ lo2, int n4)
{
    for (int i = blockIdx.x * blockDim.x + threadIdx.x; i < n4; i += gridDim.x * blockDim.x) {
        float4 v = in[i];
        bf162 h01 = __floats2bfloat162_rn(v.x, v.y);
        bf162 h23 = __floats2bfloat162_rn(v.z, v.w);
        float2 f01 = __bfloat1622float2(h01);
        float2 f23 = __bfloat1622float2(h23);
        bf162 l01 = __floats2bfloat162_rn(v.x - f01.x, v.y - f01.y);
        bf162 l23 = __floats2bfloat162_rn(v.z - f23.x, v.w - f23.y);
        hi2[2 * i] = h01; hi2[2 * i + 1] = h23;
        lo2[2 * i] = l01; lo2[2 * i + 1] = l23;
    }
}

// Transpose + split all 4 weights in one launch (grid.z selects weight).
__global__ void convert_wt_all(const float* __restrict__ W0, const float* __restrict__ W1,
                               const float* __restrict__ W2, const float* __restrict__ W3,
                               bf16* __restrict__ thi4, bf16* __restrict__ tlo4)
{
    __shared__ float t[32][33];
    const int z = blockIdx.z;
    const float* W = (z == 0) ? W0 : (z == 1) ? W1 : (z == 2) ? W2 : W3;
    bf16* thi = thi4 + (size_t)z * HID * HID;
    bf16* tlo = tlo4 + (size_t)z * HID * HID;

    int n0 = blockIdx.x * 32, k0 = blockIdx.y * 32;
    int tx = threadIdx.x, ty = threadIdx.y;
    #pragma unroll
    for (int r = 0; r < 32; r += 8)
        t[ty + r][tx] = W[(size_t)(k0 + ty + r) * HID + n0 + tx];
    __syncthreads();
    #pragma unroll
    for (int r = 0; r < 32; r += 8) {
        float v = t[tx][ty + r];
        bf16 h = __float2bfloat16(v);
        float l = v - __bfloat162float(h);
        size_t o = (size_t)(n0 + ty + r) * HID + k0 + tx;
        thi[o] = h;
        tlo[o] = __float2bfloat16(l);
    }
}

// ---------------------------------------------------------------------------
// Shared GEMM machinery (3-term bf16 split, proven round-6/7 core)
// ---------------------------------------------------------------------------
#define GKC        32
#define NCHUNK     (HID / GKC)       // 32
#define OFF_B      16384
#define STAGE_BYTES 24576
#define GEMM_SMEM  (2 * STAGE_BYTES) // 49152 (static)

__device__ __forceinline__ void load_chunk(uint32_t sbase,
    const bf16* __restrict__ Ahi, const bf16* __restrict__ Alo,
    const bf16* __restrict__ Bhi, const bf16* __restrict__ Blo,
    int by, int bx, int k0, int tid)
{
    #pragma unroll
    for (int r = 0; r < 4; r++) {
        int u    = r * 256 + tid;
        int m    = u >> 3;
        int part = (u >> 2) & 1;
        int seg  = u & 3;
        uint32_t so = SW128((uint32_t)(m * 128 + part * 64 + seg * 16));
        const bf16* src = (part ? Alo : Ahi) + (size_t)(by * 128 + m) * HID + k0 + seg * 8;
        cp16(sbase + so, src);
    }
    #pragma unroll
    for (int r = 0; r < 2; r++) {
        int u    = r * 256 + tid;
        int n    = u >> 3;
        int part = (u >> 2) & 1;
        int seg  = u & 3;
        uint32_t so = SW128((uint32_t)(n * 128 + part * 64 + seg * 16));
        const bf16* src = (part ? Blo : Bhi) + (size_t)(bx * 64 + n) * HID + k0 + seg * 8;
        cp16(sbase + OFF_B + so, src);
    }
}

// Mainloop shared by both GEMM kernels (accumulates into c[2][4][4]).
__device__ __forceinline__ void gemm_mainloop(uint32_t sb, float c[2][4][4],
    const bf16* __restrict__ Ahi, const bf16* __restrict__ Alo,
    const bf16* __restrict__ Bhi, const bf16* __restrict__ Blo,
    int by, int bx, int tid, int lane, int wid)
{
    const int wm = (wid & 3) * 32;
    const int wn = (wid >> 2) * 32;

    const int a_r    = (lane & 7) + ((lane >> 3) & 1) * 8;
    const int a_kb16 = (lane >> 4) * 16;
    const int l16    = lane & 15;
    const int b_r    = l16 & 7;
    const int b_kb16 = (l16 >> 3) * 16;

    load_chunk(sb, Ahi, Alo, Bhi, Blo, by, bx, 0, tid);
    CP_COMMIT();

    for (int ch = 0; ch < NCHUNK; ch++) {
        const uint32_t sbase = sb + (ch & 1) * STAGE_BYTES;

        if (ch + 1 < NCHUNK) {
            load_chunk(sb + ((ch + 1) & 1) * STAGE_BYTES,
                       Ahi, Alo, Bhi, Blo, by, bx, (ch + 1) * GKC, tid);
            CP_COMMIT();
            CP_WAIT1();
        } else {
            CP_WAIT0();
        }
        __syncthreads();

        const uint32_t ab = sbase;
        const uint32_t bb = sbase + OFF_B;

        #pragma unroll
        for (int ks = 0; ks < 2; ks++) {
            const int kb = ks * 32;

            uint32_t Ah[2][4], Al[2][4];
            #pragma unroll
            for (int mt = 0; mt < 2; mt++) {
                int row = wm + mt * 16 + a_r;
                uint32_t colh = (uint32_t)((kb + a_kb16)      ^ ((row & 7) << 4));
                uint32_t coll = (uint32_t)((kb + a_kb16 + 64) ^ ((row & 7) << 4));
                ldsm4(Ah[mt], ab + (uint32_t)(row * 128) + colh);
                ldsm4(Al[mt], ab + (uint32_t)(row * 128) + coll);
            }

            #pragma unroll
            for (int nt = 0; nt < 4; nt++) {
                int nrow = wn + nt * 8 + b_r;
                uint32_t colh = (uint32_t)((kb + b_kb16)      ^ ((nrow & 7) << 4));
                uint32_t coll = (uint32_t)((kb + b_kb16 + 64) ^ ((nrow & 7) << 4));
                uint32_t Bh[2], Bl[2];
                ldsm2(Bh, bb + (uint32_t)(nrow * 128) + colh);
                ldsm2(Bl, bb + (uint32_t)(nrow * 128) + coll);
                mma16816(c[0][nt], Ah[0], Bh);
                mma16816(c[1][nt], Ah[1], Bh);
                mma16816(c[0][nt], Ah[0], Bl);
                mma16816(c[1][nt], Ah[1], Bl);
                mma16816(c[0][nt], Al[0], Bh);
                mma16816(c[1][nt], Al[1], Bh);
            }
        }

        __syncthreads();
    }
}

// Fused Q/K/V projection: grid.x = 48 (panel = bx>>4), writes bf16 hi/lo.
__global__ __launch_bounds__(256)
void gemm_qkv(const bf16* __restrict__ Ahi, const bf16* __restrict__ Alo,
              const bf16* __restrict__ wt4hi, const bf16* __restrict__ wt4lo,
              const float* __restrict__ bq, const float* __restrict__ bk,
              const float* __restrict__ bv,
              bf16* __restrict__ qhi, bf16* __restrict__ qlo,
              bf16* __restrict__ khi, bf16* __restrict__ klo,
              bf16* __restrict__ vhi, bf16* __restrict__ vlo)
{
    __shared__ __align__(128) char smem[GEMM_SMEM];
    uint32_t sb = smem_u32(smem);
    const int tid  = threadIdx.x;
    const int lane = tid & 31;
    const int wid  = tid >> 5;
    const int panel = blockIdx.x >> 4;
    const int bx    = blockIdx.x & 15;
    const int by    = blockIdx.y;

    const bf16* Bhi = wt4hi + (size_t)panel * HID * HID;
    const bf16* Blo = wt4lo + (size_t)panel * HID * HID;
    const float* bias = (panel == 0) ? bq : (panel == 1) ? bk : bv;
    bf16* Ohi = (panel == 0) ? qhi : (panel == 1) ? khi : vhi;
    bf16* Olo = (panel == 0) ? qlo : (panel == 1) ? klo : vlo;
    const float scale = (panel == 0) ? 0.125f : 1.0f;

    float c[2][4][4];
    #pragma unroll
    for (int mt = 0; mt < 2; mt++)
        #pragma unroll
        for (int nt = 0; nt < 4; nt++)
            #pragma unroll
            for (int i = 0; i < 4; i++) c[mt][nt][i] = 0.0f;

    gemm_mainloop(sb, c, Ahi, Alo, Bhi, Blo, by, bx, tid, lane, wid);

    const int wm = (wid & 3) * 32;
    const int wn = (wid >> 2) * 32;
    const int crow0 = by * 128 + wm + (lane >> 2);
    const int ccol0 = bx * 64 + wn + (lane & 3) * 2;
    #pragma unroll
    for (int nt = 0; nt < 4; nt++) {
        float2 bb = *(const float2*)&bias[ccol0 + nt * 8];
        #pragma unroll
        for (int mt = 0; mt < 2; mt++) {
            #pragma unroll
            for (int h = 0; h < 2; h++) {
                int row = crow0 + mt * 16 + h * 8;
                float vx = (c[mt][nt][2 * h + 0] + bb.x) * scale;
                float vy = (c[mt][nt][2 * h + 1] + bb.y) * scale;
                size_t idx = (size_t)row * HID + ccol0 + nt * 8;
                bf162 hi2 = __floats2bfloat162_rn(vx, vy);
                float2 hf = __bfloat1622float2(hi2);
                bf162 lo2 = __floats2bfloat162_rn(vx - hf.x, vy - hf.y);
                *(bf162*)&Ohi[idx] = hi2;
                *(bf162*)&Olo[idx] = lo2;
            }
        }
    }
}

// O-projection GEMM: fp32 output + bias.
__global__ __launch_bounds__(256)
void gemm_out(const bf16* __restrict__ Ahi, const bf16* __restrict__ Alo,
              const bf16* __restrict__ Bhi, const bf16* __restrict__ Blo,
              const float* __restrict__ bias, float* __restrict__ Cf)
{
    __shared__ __align__(128) char smem[GEMM_SMEM];
    uint32_t sb = smem_u32(smem);
    const int tid  = threadIdx.x;
    const int lane = tid & 31;
    const int wid  = tid >> 5;
    const int bx = blockIdx.x, by = blockIdx.y;

    float c[2][4][4];
    #pragma unroll
    for (int mt = 0; mt < 2; mt++)
        #pragma unroll
        for (int nt = 0; nt < 4; nt++)
            #pragma unroll
            for (int i = 0; i < 4; i++) c[mt][nt][i] = 0.0f;

    gemm_mainloop(sb, c, Ahi, Alo, Bhi, Blo, by, bx, tid, lane, wid);

    const int wm = (wid & 3) * 32;
    const int wn = (wid >> 2) * 32;
    const int crow0 = by * 128 + wm + (lane >> 2);
    const int ccol0 = bx * 64 + wn + (lane & 3) * 2;
    #pragma unroll
    for (int nt = 0; nt < 4; nt++) {
        float2 bb = *(const float2*)&bias[ccol0 + nt * 8];
        #pragma unroll
        for (int mt = 0; mt < 2; mt++) {
            #pragma unroll
            for (int h = 0; h < 2; h++) {
                int row = crow0 + mt * 16 + h * 8;
                float2 v;
                v.x = c[mt][nt][2 * h + 0] + bb.x;
                v.y = c[mt][nt][2 * h + 1] + bb.y;
                *(float2*)&Cf[(size_t)row * HID + ccol0 + nt * 8] = v;
            }
        }
    }
}

// ---------------------------------------------------------------------------
// Tensor-core flash attention, 32-key tiles, double-buffered K/V.
// Per CTA: 64 queries x one (b,h). 4 warps x 16 query rows.
// smem: Q hi/lo 16K persistent + 2 stages x (K hi/lo 8K + V hi/lo 8K) = 48K.
// ---------------------------------------------------------------------------
#define KT    32
#define SQ_HI 0
#define SQ_LO 8192
#define STG0  16384
#define STG_SZ 16384
#define SK_HI 0
#define SK_LO 4096
#define SV_HI 8192
#define SV_LO 12288
#define ATT_SMEM 49152

__device__ __forceinline__ void att_load_kv(uint32_t stg, size_t kvb,
    const bf16* __restrict__ Khi, const bf16* __restrict__ Klo,
    const bf16* __restrict__ Vhi, const bf16* __restrict__ Vlo, int tid)
{
    #pragma unroll
    for (int r = 0; r < 2; r++) {
        int u = r * 128 + tid;
        int row = u >> 3, seg = u & 7;
        uint32_t so = SW128((uint32_t)(row * 128 + seg * 16));
        const size_t g = kvb + (size_t)row * HID + seg * 8;
        cp16(stg + SK_HI + so, Khi + g);
        cp16(stg + SK_LO + so, Klo + g);
        cp16(stg + SV_HI + so, Vhi + g);
        cp16(stg + SV_LO + so, Vlo + g);
    }
}

__global__ __launch_bounds__(128)
void flash_attn_mma(const bf16* __restrict__ Qhi, const bf16* __restrict__ Qlo,
                    const bf16* __restrict__ Khi, const bf16* __restrict__ Klo,
                    const bf16* __restrict__ Vhi, const bf16* __restrict__ Vlo,
                    bf16* __restrict__ Chi, bf16* __restrict__ Clo)
{
    __shared__ __align__(128) char smem[ATT_SMEM];
    uint32_t sb = smem_u32(smem);
    const int tid  = threadIdx.x;
    const int lane = tid & 31;
    const int wid  = tid >> 5;
    const int q0 = blockIdx.x * 64;
    const int h  = blockIdx.y;
    const int b  = blockIdx.z;

    const size_t qg  = ((size_t)(b * SEQ + q0)) * HID + h * HDIM;
    const size_t kvg = ((size_t)(b * SEQ)) * HID + h * HDIM;

    // Load Q tile (64 rows x 64 bf16, hi & lo) -> group 0
    #pragma unroll
    for (int r = 0; r < 4; r++) {
        int u = r * 128 + tid;
        int row = u >> 3, seg = u & 7;
        uint32_t so = SW128((uint32_t)(row * 128 + seg * 16));
        cp16(sb + SQ_HI + so, Qhi + qg + (size_t)row * HID + seg * 8);
        cp16(sb + SQ_LO + so, Qlo + qg + (size_t)row * HID + seg * 8);
    }
    CP_COMMIT();

    // Load KV tile 0 -> stage 0 (group 1)
    att_load_kv(sb + STG0, kvg, Khi, Klo, Vhi, Vlo, tid);
    CP_COMMIT();

    const int wm = wid * 16;
    const int a_r    = (lane & 7) + ((lane >> 3) & 1) * 8;
    const int a_kb16 = (lane >> 4) * 16;
    const int b_r    = lane & 7;
    const int b_kb16 = ((lane >> 3) & 1) * 16;

    CP_WAIT1();              // Q resident (KV0 may be in flight)
    __syncthreads();

    // Cache Q A-fragments (4 k16-chunks, hi & lo)
    uint32_t qh[4][4], ql[4][4];
    #pragma unroll
    for (int kc = 0; kc < 4; kc++) {
        int row = wm + a_r;
        uint32_t col = (uint32_t)((kc * 32 + a_kb16) ^ ((row & 7) << 4));
        ldsm4(qh[kc], sb + SQ_HI + (uint32_t)(row * 128) + col);
        ldsm4(ql[kc], sb + SQ_LO + (uint32_t)(row * 128) + col);
    }

    float m0 = -INFINITY, m1 = -INFINITY, l0 = 0.0f, l1 = 0.0f;
    float o[8][4];
    #pragma unroll
    for (int nt = 0; nt < 8; nt++)
        #pragma unroll
        for (int i = 0; i < 4; i++) o[nt][i] = 0.0f;

    for (int kt = 0; kt < SEQ / KT; kt++) {
        // Prefetch next tile into the other stage
        if (kt + 1 < SEQ / KT) {
            att_load_kv(sb + STG0 + ((kt + 1) & 1) * STG_SZ,
                        kvg + (size_t)((kt + 1) * KT) * HID,
                        Khi, Klo, Vhi, Vlo, tid);
            CP_COMMIT();
            CP_WAIT1();      // tile kt resident
        } else {
            CP_WAIT0();
        }
        __syncthreads();

        const uint32_t stg = sb + STG0 + (kt & 1) * STG_SZ;

        // ---- S = Q @ K^T (3 split terms), 32 keys ----
        float s[4][4];
        #pragma unroll
        for (int nt = 0; nt < 4; nt++)
            #pragma unroll
            for (int i = 0; i < 4; i++) s[nt][i] = 0.0f;

        #pragma unroll
        for (int kc = 0; kc < 4; kc++) {
            #pragma unroll
            for (int ntp = 0; ntp < 2; ntp++) {
                int nrow = ntp * 16 + ((lane >> 4) & 1) * 8 + b_r;
                uint32_t col = (uint32_t)((kc * 32 + b_kb16) ^ ((nrow & 7) << 4));
                uint32_t kh[4], kl[4];
                ldsm4(kh, stg + SK_HI + (uint32_t)(nrow * 128) + col);
                ldsm4(kl, stg + SK_LO + (uint32_t)(nrow * 128) + col);
                mma16816(s[2 * ntp],     qh[kc], kh);
                mma16816(s[2 * ntp],     qh[kc], kl);
                mma16816(s[2 * ntp],     ql[kc], kh);
                mma16816(s[2 * ntp + 1], qh[kc], kh + 2);
                mma16816(s[2 * ntp + 1], qh[kc], kl + 2);
                mma16816(s[2 * ntp + 1], ql[kc], kh + 2);
            }
        }

        // ---- Online softmax ----
        float rmax0 = -INFINITY, rmax1 = -INFINITY;
        #pragma unroll
        for (int nt = 0; nt < 4; nt++) {
            rmax0 = fmaxf(rmax0, fmaxf(s[nt][0], s[nt][1]));
            rmax1 = fmaxf(rmax1, fmaxf(s[nt][2], s[nt][3]));
        }
        rmax0 = fmaxf(rmax0, __shfl_xor_sync(0xffffffffu, rmax0, 1));
        rmax0 = fmaxf(rmax0, __shfl_xor_sync(0xffffffffu, rmax0, 2));
        rmax1 = fmaxf(rmax1, __shfl_xor_sync(0xffffffffu, rmax1, 1));
        rmax1 = fmaxf(rmax1, __shfl_xor_sync(0xffffffffu, rmax1, 2));

        float mt0 = fmaxf(m0, rmax0), mt1 = fmaxf(m1, rmax1);
        float f0 = __expf(m0 - mt0),  f1 = __expf(m1 - mt1);
        m0 = mt0; m1 = mt1;

        float ls0 = 0.0f, ls1 = 0.0f;
        #pragma unroll
        for (int nt = 0; nt < 4; nt++) {
            s[nt][0] = __expf(s[nt][0] - m0);
            s[nt][1] = __expf(s[nt][1] - m0);
            s[nt][2] = __expf(s[nt][2] - m1);
            s[nt][3] = __expf(s[nt][3] - m1);
            ls0 += s[nt][0] + s[nt][1];
            ls1 += s[nt][2] + s[nt][3];
        }
        ls0 += __shfl_xor_sync(0xffffffffu, ls0, 1);
        ls0 += __shfl_xor_sync(0xffffffffu, ls0, 2);
        ls1 += __shfl_xor_sync(0xffffffffu, ls1, 1);
        ls1 += __shfl_xor_sync(0xffffffffu, ls1, 2);
        l0 = l0 * f0 + ls0;
        l1 = l1 * f1 + ls1;

        #pragma unroll
        for (int nt = 0; nt < 8; nt++) {
            o[nt][0] *= f0; o[nt][1] *= f0;
            o[nt][2] *= f1; o[nt][3] *= f1;
        }

        // ---- Pack P into A-fragments (hi + lo split) ----
        uint32_t phi[2][4], plo[2][4];
        #pragma unroll
        for (int kj = 0; kj < 2; kj++) {
            #pragma unroll
            for (int half = 0; half < 2; half++) {
                int t = 2 * kj + half;
                bf162 h0 = __floats2bfloat162_rn(s[t][0], s[t][1]);
                float2 hf0 = __bfloat1622float2(h0);
                bf162 lo0 = __floats2bfloat162_rn(s[t][0] - hf0.x, s[t][1] - hf0.y);
                bf162 h1 = __floats2bfloat162_rn(s[t][2], s[t][3]);
                float2 hf1 = __bfloat1622float2(h1);
                bf162 lo1 = __floats2bfloat162_rn(s[t][2] - hf1.x, s[t][3] - hf1.y);
                phi[kj][2 * half + 0] = *(uint32_t*)&h0;
                phi[kj][2 * half + 1] = *(uint32_t*)&h1;
                plo[kj][2 * half + 0] = *(uint32_t*)&lo0;
                plo[kj][2 * half + 1] = *(uint32_t*)&lo1;
            }
        }

        // ---- O += P @ V (3 split terms), V via ldmatrix.trans ----
        #pragma unroll
        for (int kj = 0; kj < 2; kj++) {
            #pragma unroll
            for (int ntv = 0; ntv < 4; ntv++) {
                uint32_t voff = SW128((uint32_t)((kj * 16 + (lane & 15)) * 128 +
                                                 (ntv * 16 + 8 * (lane >> 4)) * 2));
                uint32_t vh[4], vl[4];
                ldsm4t(vh, stg + SV_HI + voff);
                ldsm4t(vl, stg + SV_LO + voff);
                mma16816(o[2 * ntv],     phi[kj], vh);
                mma16816(o[2 * ntv],     phi[kj], vl);
                mma16816(o[2 * ntv],     plo[kj], vh);
                mma16816(o[2 * ntv + 1], phi[kj], vh + 2);
                mma16816(o[2 * ntv + 1], phi[kj], vl + 2);
                mma16816(o[2 * ntv + 1], plo[kj], vh + 2);
            }
        }

        __syncthreads();   // all warps done reading before next prefetch overwrites
    }

    // ---- Finalize: divide by l, split to bf16 hi/lo, store ----
    const float inv0 = 1.0f / l0, inv1 = 1.0f / l1;
    const int row0 = q0 + wm + (lane >> 2);
    const int colb = (lane & 3) * 2;
    #pragma unroll
    for (int nt = 0; nt < 8; nt++) {
        {
            float vx = o[nt][0] * inv0, vy = o[nt][1] * inv0;
            size_t idx = ((size_t)(b * SEQ + row0)) * HID + h * HDIM + nt * 8 + colb;
            bf162 hi2 = __floats2bfloat162_rn(vx, vy);
            float2 hf = __bfloat1622float2(hi2);
            bf162 lo2 = __floats2bfloat162_rn(vx - hf.x, vy - hf.y);
            *(bf162*)&Chi[idx] = hi2;
            *(bf162*)&Clo[idx] = lo2;
        }
        {
            float vx = o[nt][2] * inv1, vy = o[nt][3] * inv1;
            size_t idx = ((size_t)(b * SEQ + row0 + 8)) * HID + h * HDIM + nt * 8 + colb;
            bf162 hi2 = __floats2bfloat162_rn(vx, vy);
            float2 hf = __bfloat1622float2(hi2);
            bf162 lo2 = __floats2bfloat162_rn(vx - hf.x, vy - hf.y);
            *(bf162*)&Chi[idx] = hi2;
            *(bf162*)&Clo[idx] = lo2;
        }
    }
}

// ---------------------------------------------------------------------------
// Launch (no cudaFuncSetAttribute, no dynamic smem)
// ---------------------------------------------------------------------------
extern "C" void kernel_launch(void* const* d_in, const int* in_sizes, int n_in,
                              void* d_out, int out_size)
{
    const float* x  = (const float*)d_in[0];
    const float* Wq = (const float*)d_in[1];
    const float* bq = (const float*)d_in[2];
    const float* Wk = (const float*)d_in[3];
    const float* bk = (const float*)d_in[4];
    const float* Wv = (const float*)d_in[5];
    const float* bv = (const float*)d_in[6];
    const float* Wo = (const float*)d_in[7];
    const float* bo = (const float*)d_in[8];
    float* out = (float*)d_out;

    bf16 *xhi, *xlo, *qhi, *qlo, *khi, *klo, *vhi, *vlo, *chi, *clo, *wt4hi, *wt4lo;
    cudaGetSymbolAddress((void**)&xhi, g_xhi);
    cudaGetSymbolAddress((void**)&xlo, g_xlo);
    cudaGetSymbolAddress((void**)&qhi, g_qhi);
    cudaGetSymbolAddress((void**)&qlo, g_qlo);
    cudaGetSymbolAddress((void**)&khi, g_khi);
    cudaGetSymbolAddress((void**)&klo, g_klo);
    cudaGetSymbolAddress((void**)&vhi, g_vhi);
    cudaGetSymbolAddress((void**)&vlo, g_vlo);
    cudaGetSymbolAddress((void**)&chi, g_chi);
    cudaGetSymbolAddress((void**)&clo, g_clo);
    cudaGetSymbolAddress((void**)&wt4hi, g_wt4hi);
    cudaGetSymbolAddress((void**)&wt4lo, g_wt4lo);

    const int n4x = MROWS * HID / 4;
    dim3 wtg(HID / 32, HID / 32, 4);
    dim3 wtb(32, 8);

    convert_split<<<2048, 256>>>((const float4*)x, (bf162*)xhi, (bf162*)xlo, n4x);
    convert_wt_all<<<wtg, wtb>>>(Wq, Wk, Wv, Wo, wt4hi, wt4lo);

    dim3 qkvgrid(48, MROWS / 128);   // (48, 64): 3 panels x 16 n-tiles
    gemm_qkv<<<qkvgrid, 256>>>(xhi, xlo, wt4hi, wt4lo, bq, bk, bv,
                               qhi, qlo, khi, klo, vhi, vlo);

    dim3 agrid(SEQ / 64, NHEAD, BATCH);   // (16, 16, 8)
    flash_attn_mma<<<agrid, 128>>>(qhi, qlo, khi, klo, vhi, vlo, chi, clo);

    dim3 ogrid(HID / 64, MROWS / 128);    // (16, 64)
    gemm_out<<<ogrid, 256>>>(chi, clo,
                             wt4hi + (size_t)3 * HID * HID,
                             wt4lo + (size_t)3 * HID * HID, bo, out);
}

// round 9
// speedup vs baseline: 3.6776x; 1.0496x over previous
#include <cuda_runtime.h>
#include <cuda_bf16.h>
#include <math.h>
#include <stdint.h>

// ---------------------------------------------------------------------------
// Problem constants
// ---------------------------------------------------------------------------
#define BATCH 8
#define SEQ   1024
#define HID   1024
#define NHEAD 16
#define HDIM  64
#define MROWS (BATCH * SEQ)   // 8192

typedef __nv_bfloat16  bf16;
typedef __nv_bfloat162 bf162;

// ---------------------------------------------------------------------------
// Scratch (device globals; no allocation allowed)
// ---------------------------------------------------------------------------
__device__ bf16  g_xhi[MROWS * HID];
__device__ bf16  g_xlo[MROWS * HID];
__device__ bf16  g_qhi[MROWS * HID];
__device__ bf16  g_qlo[MROWS * HID];
__device__ bf16  g_khi[MROWS * HID];
__device__ bf16  g_klo[MROWS * HID];
__device__ bf16  g_vhi[MROWS * HID];
__device__ bf16  g_vlo[MROWS * HID];
__device__ bf16  g_chi[MROWS * HID];
__device__ bf16  g_clo[MROWS * HID];
__device__ bf16  g_wt4hi[4 * HID * HID];   // transposed weights hi [N,K], 4 panels
__device__ bf16  g_wt4lo[4 * HID * HID];   // transposed weights lo

// ---------------------------------------------------------------------------
// Helpers
// ---------------------------------------------------------------------------
__device__ __forceinline__ uint32_t smem_u32(const void* p) {
    uint32_t a;
    asm("{ .reg .u64 t; cvta.to.shared.u64 t, %1; cvt.u32.u64 %0, t; }"
        : "=r"(a) : "l"(p));
    return a;
}

#define SW128(o) ((o) ^ (((o) >> 3) & 0x70))

__device__ __forceinline__ void cp16(uint32_t smem, const void* g) {
    asm volatile("cp.async.cg.shared.global [%0], [%1], 16;" :: "r"(smem), "l"(g));
}
#define CP_COMMIT()  asm volatile("cp.async.commit_group;" ::: "memory")
#define CP_WAIT1()   asm volatile("cp.async.wait_group 1;" ::: "memory")
#define CP_WAIT0()   asm volatile("cp.async.wait_group 0;" ::: "memory")

__device__ __forceinline__ void ldsm4(uint32_t* r, uint32_t addr) {
    asm volatile("ldmatrix.sync.aligned.m8n8.x4.shared.b16 {%0,%1,%2,%3}, [%4];"
        : "=r"(r[0]), "=r"(r[1]), "=r"(r[2]), "=r"(r[3]) : "r"(addr));
}
__device__ __forceinline__ void ldsm4t(uint32_t* r, uint32_t addr) {
    asm volatile("ldmatrix.sync.aligned.m8n8.x4.trans.shared.b16 {%0,%1,%2,%3}, [%4];"
        : "=r"(r[0]), "=r"(r[1]), "=r"(r[2]), "=r"(r[3]) : "r"(addr));
}
__device__ __forceinline__ void mma16816(float* c, const uint32_t* a, const uint32_t* b) {
    asm volatile("mma.sync.aligned.m16n8k16.row.col.f32.bf16.bf16.f32 "
        "{%0,%1,%2,%3}, {%4,%5,%6,%7}, {%8,%9}, {%0,%1,%2,%3};"
        : "+f"(c[0]), "+f"(c[1]), "+f"(c[2]), "+f"(c[3])
        : "r"(a[0]), "r"(a[1]), "r"(a[2]), "r"(a[3]), "r"(b[0]), "r"(b[1]));
}

// ---------------------------------------------------------------------------
// Split-convert: fp32 -> (bf16 hi, bf16 lo) with lo = x - float(hi)
// ---------------------------------------------------------------------------
__global__ void convert_split(const float4* __restrict__ in,
                              bf162* __restrict__ hi2, bf162* __restrict__ lo2, int n4)
{
    for (int i = blockIdx.x * blockDim.x + threadIdx.x; i < n4; i += gridDim.x * blockDim.x) {
        float4 v = in[i];
        bf162 h01 = __floats2bfloat162_rn(v.x, v.y);
        bf162 h23 = __floats2bfloat162_rn(v.z, v.w);
        float2 f01 = __bfloat1622float2(h01);
        float2 f23 = __bfloat1622float2(h23);
        bf162 l01 = __floats2bfloat162_rn(v.x - f01.x, v.y - f01.y);
        bf162 l23 = __floats2bfloat162_rn(v.z - f23.x, v.w - f23.y);
        hi2[2 * i] = h01; hi2[2 * i + 1] = h23;
        lo2[2 * i] = l01; lo2[2 * i + 1] = l23;
    }
}

// Transpose + split all 4 weights in one launch (grid.z selects weight).
__global__ void convert_wt_all(const float* __restrict__ W0, const float* __restrict__ W1,
                               const float* __restrict__ W2, const float* __restrict__ W3,
                               bf16* __restrict__ thi4, bf16* __restrict__ tlo4)
{
    __shared__ float t[32][33];
    const int z = blockIdx.z;
    const float* W = (z == 0) ? W0 : (z == 1) ? W1 : (z == 2) ? W2 : W3;
    bf16* thi = thi4 + (size_t)z * HID * HID;
    bf16* tlo = tlo4 + (size_t)z * HID * HID;

    int n0 = blockIdx.x * 32, k0 = blockIdx.y * 32;
    int tx = threadIdx.x, ty = threadIdx.y;
    #pragma unroll
    for (int r = 0; r < 32; r += 8)
        t[ty + r][tx] = W[(size_t)(k0 + ty + r) * HID + n0 + tx];
    __syncthreads();
    #pragma unroll
    for (int r = 0; r < 32; r += 8) {
        float v = t[tx][ty + r];
        bf16 h = __float2bfloat16(v);
        float l = v - __bfloat162float(h);
        size_t o = (size_t)(n0 + ty + r) * HID + k0 + tx;
        thi[o] = h;
        tlo[o] = __float2bfloat16(l);
    }
}

// ---------------------------------------------------------------------------
// Shared GEMM machinery (3-term bf16 split)
// B fragments now via ldsm4 (two n-tiles per instruction).
// ---------------------------------------------------------------------------
#define GKC        32
#define NCHUNK     (HID / GKC)       // 32
#define OFF_B      16384
#define STAGE_BYTES 24576
#define GEMM_SMEM  (2 * STAGE_BYTES) // 49152 (static)

__device__ __forceinline__ void load_chunk(uint32_t sbase,
    const bf16* __restrict__ Ahi, const bf16* __restrict__ Alo,
    const bf16* __restrict__ Bhi, const bf16* __restrict__ Blo,
    int by, int bx, int k0, int tid)
{
    #pragma unroll
    for (int r = 0; r < 4; r++) {
        int u    = r * 256 + tid;
        int m    = u >> 3;
        int part = (u >> 2) & 1;
        int seg  = u & 3;
        uint32_t so = SW128((uint32_t)(m * 128 + part * 64 + seg * 16));
        const bf16* src = (part ? Alo : Ahi) + (size_t)(by * 128 + m) * HID + k0 + seg * 8;
        cp16(sbase + so, src);
    }
    #pragma unroll
    for (int r = 0; r < 2; r++) {
        int u    = r * 256 + tid;
        int n    = u >> 3;
        int part = (u >> 2) & 1;
        int seg  = u & 3;
        uint32_t so = SW128((uint32_t)(n * 128 + part * 64 + seg * 16));
        const bf16* src = (part ? Blo : Bhi) + (size_t)(bx * 64 + n) * HID + k0 + seg * 8;
        cp16(sbase + OFF_B + so, src);
    }
}

// Mainloop shared by both GEMM kernels (accumulates into c[2][4][4]).
__device__ __forceinline__ void gemm_mainloop(uint32_t sb, float c[2][4][4],
    const bf16* __restrict__ Ahi, const bf16* __restrict__ Alo,
    const bf16* __restrict__ Bhi, const bf16* __restrict__ Blo,
    int by, int bx, int tid, int lane, int wid)
{
    const int wm = (wid & 3) * 32;
    const int wn = (wid >> 2) * 32;

    const int a_r    = (lane & 7) + ((lane >> 3) & 1) * 8;
    const int a_kb16 = (lane >> 4) * 16;
    // ldsm4 B geometry: lanes 0-7 tile0 k-lo, 8-15 tile0 k-hi,
    //                   16-23 tile1 k-lo, 24-31 tile1 k-hi
    const int b_r4   = ((lane >> 4) & 1) * 8 + (lane & 7);
    const int b_kb16 = ((lane >> 3) & 1) * 16;

    load_chunk(sb, Ahi, Alo, Bhi, Blo, by, bx, 0, tid);
    CP_COMMIT();

    for (int ch = 0; ch < NCHUNK; ch++) {
        const uint32_t sbase = sb + (ch & 1) * STAGE_BYTES;

        if (ch + 1 < NCHUNK) {
            load_chunk(sb + ((ch + 1) & 1) * STAGE_BYTES,
                       Ahi, Alo, Bhi, Blo, by, bx, (ch + 1) * GKC, tid);
            CP_COMMIT();
            CP_WAIT1();
        } else {
            CP_WAIT0();
        }
        __syncthreads();

        const uint32_t ab = sbase;
        const uint32_t bb = sbase + OFF_B;

        #pragma unroll
        for (int ks = 0; ks < 2; ks++) {
            const int kb = ks * 32;

            uint32_t Ah[2][4], Al[2][4];
            #pragma unroll
            for (int mt = 0; mt < 2; mt++) {
                int row = wm + mt * 16 + a_r;
                uint32_t colh = (uint32_t)((kb + a_kb16)      ^ ((row & 7) << 4));
                uint32_t coll = (uint32_t)((kb + a_kb16 + 64) ^ ((row & 7) << 4));
                ldsm4(Ah[mt], ab + (uint32_t)(row * 128) + colh);
                ldsm4(Al[mt], ab + (uint32_t)(row * 128) + coll);
            }

            #pragma unroll
            for (int ntp = 0; ntp < 2; ntp++) {       // pairs of n8 tiles
                int nrow = wn + ntp * 16 + b_r4;
                uint32_t colh = (uint32_t)((kb + b_kb16)      ^ ((nrow & 7) << 4));
                uint32_t coll = (uint32_t)((kb + b_kb16 + 64) ^ ((nrow & 7) << 4));
                uint32_t Bh[4], Bl[4];
                ldsm4(Bh, bb + (uint32_t)(nrow * 128) + colh);
                ldsm4(Bl, bb + (uint32_t)(nrow * 128) + coll);
                #pragma unroll
                for (int half = 0; half < 2; half++) {
                    int nt = 2 * ntp + half;
                    mma16816(c[0][nt], Ah[0], Bh + 2 * half);
                    mma16816(c[1][nt], Ah[1], Bh + 2 * half);
                    mma16816(c[0][nt], Ah[0], Bl + 2 * half);
                    mma16816(c[1][nt], Ah[1], Bl + 2 * half);
                    mma16816(c[0][nt], Al[0], Bh + 2 * half);
                    mma16816(c[1][nt], Al[1], Bh + 2 * half);
                }
            }
        }

        __syncthreads();
    }
}

// Fused Q/K/V projection: grid.x = 48 (panel = bx>>4), writes bf16 hi/lo.
__global__ __launch_bounds__(256)
void gemm_qkv(const bf16* __restrict__ Ahi, const bf16* __restrict__ Alo,
              const bf16* __restrict__ wt4hi, const bf16* __restrict__ wt4lo,
              const float* __restrict__ bq, const float* __restrict__ bk,
              const float* __restrict__ bv,
              bf16* __restrict__ qhi, bf16* __restrict__ qlo,
              bf16* __restrict__ khi, bf16* __restrict__ klo,
              bf16* __restrict__ vhi, bf16* __restrict__ vlo)
{
    __shared__ __align__(128) char smem[GEMM_SMEM];
    uint32_t sb = smem_u32(smem);
    const int tid  = threadIdx.x;
    const int lane = tid & 31;
    const int wid  = tid >> 5;
    const int panel = blockIdx.x >> 4;
    const int bx    = blockIdx.x & 15;
    const int by    = blockIdx.y;

    const bf16* Bhi = wt4hi + (size_t)panel * HID * HID;
    const bf16* Blo = wt4lo + (size_t)panel * HID * HID;
    const float* bias = (panel == 0) ? bq : (panel == 1) ? bk : bv;
    bf16* Ohi = (panel == 0) ? qhi : (panel == 1) ? khi : vhi;
    bf16* Olo = (panel == 0) ? qlo : (panel == 1) ? klo : vlo;
    const float scale = (panel == 0) ? 0.125f : 1.0f;

    float c[2][4][4];
    #pragma unroll
    for (int mt = 0; mt < 2; mt++)
        #pragma unroll
        for (int nt = 0; nt < 4; nt++)
            #pragma unroll
            for (int i = 0; i < 4; i++) c[mt][nt][i] = 0.0f;

    gemm_mainloop(sb, c, Ahi, Alo, Bhi, Blo, by, bx, tid, lane, wid);

    const int wm = (wid & 3) * 32;
    const int wn = (wid >> 2) * 32;
    const int crow0 = by * 128 + wm + (lane >> 2);
    const int ccol0 = bx * 64 + wn + (lane & 3) * 2;
    #pragma unroll
    for (int nt = 0; nt < 4; nt++) {
        float2 bb = *(const float2*)&bias[ccol0 + nt * 8];
        #pragma unroll
        for (int mt = 0; mt < 2; mt++) {
            #pragma unroll
            for (int h = 0; h < 2; h++) {
                int row = crow0 + mt * 16 + h * 8;
                float vx = (c[mt][nt][2 * h + 0] + bb.x) * scale;
                float vy = (c[mt][nt][2 * h + 1] + bb.y) * scale;
                size_t idx = (size_t)row * HID + ccol0 + nt * 8;
                bf162 hi2 = __floats2bfloat162_rn(vx, vy);
                float2 hf = __bfloat1622float2(hi2);
                bf162 lo2 = __floats2bfloat162_rn(vx - hf.x, vy - hf.y);
                *(bf162*)&Ohi[idx] = hi2;
                *(bf162*)&Olo[idx] = lo2;
            }
        }
    }
}

// O-projection GEMM: fp32 output + bias.
__global__ __launch_bounds__(256)
void gemm_out(const bf16* __restrict__ Ahi, const bf16* __restrict__ Alo,
              const bf16* __restrict__ Bhi, const bf16* __restrict__ Blo,
              const float* __restrict__ bias, float* __restrict__ Cf)
{
    __shared__ __align__(128) char smem[GEMM_SMEM];
    uint32_t sb = smem_u32(smem);
    const int tid  = threadIdx.x;
    const int lane = tid & 31;
    const int wid  = tid >> 5;
    const int bx = blockIdx.x, by = blockIdx.y;

    float c[2][4][4];
    #pragma unroll
    for (int mt = 0; mt < 2; mt++)
        #pragma unroll
        for (int nt = 0; nt < 4; nt++)
            #pragma unroll
            for (int i = 0; i < 4; i++) c[mt][nt][i] = 0.0f;

    gemm_mainloop(sb, c, Ahi, Alo, Bhi, Blo, by, bx, tid, lane, wid);

    const int wm = (wid & 3) * 32;
    const int wn = (wid >> 2) * 32;
    const int crow0 = by * 128 + wm + (lane >> 2);
    const int ccol0 = bx * 64 + wn + (lane & 3) * 2;
    #pragma unroll
    for (int nt = 0; nt < 4; nt++) {
        float2 bb = *(const float2*)&bias[ccol0 + nt * 8];
        #pragma unroll
        for (int mt = 0; mt < 2; mt++) {
            #pragma unroll
            for (int h = 0; h < 2; h++) {
                int row = crow0 + mt * 16 + h * 8;
                float2 v;
                v.x = c[mt][nt][2 * h + 0] + bb.x;
                v.y = c[mt][nt][2 * h + 1] + bb.y;
                *(float2*)&Cf[(size_t)row * HID + ccol0 + nt * 8] = v;
            }
        }
    }
}

// ---------------------------------------------------------------------------
// Tensor-core flash attention, 32-key tiles, double-buffered K/V.
// Per CTA: 64 queries x one (b,h). 4 warps x 16 query rows.
// Q-hi fragments cached in regs; Q-lo fragments reloaded from the persistent
// Q smem tile each use (saves ~16 regs -> 4 CTAs/SM).
// ---------------------------------------------------------------------------
#define KT    32
#define SQ_HI 0
#define SQ_LO 8192
#define STG0  16384
#define STG_SZ 16384
#define SK_HI 0
#define SK_LO 4096
#define SV_HI 8192
#define SV_LO 12288
#define ATT_SMEM 49152

__device__ __forceinline__ void att_load_kv(uint32_t stg, size_t kvb,
    const bf16* __restrict__ Khi, const bf16* __restrict__ Klo,
    const bf16* __restrict__ Vhi, const bf16* __restrict__ Vlo, int tid)
{
    #pragma unroll
    for (int r = 0; r < 2; r++) {
        int u = r * 128 + tid;
        int row = u >> 3, seg = u & 7;
        uint32_t so = SW128((uint32_t)(row * 128 + seg * 16));
        const size_t g = kvb + (size_t)row * HID + seg * 8;
        cp16(stg + SK_HI + so, Khi + g);
        cp16(stg + SK_LO + so, Klo + g);
        cp16(stg + SV_HI + so, Vhi + g);
        cp16(stg + SV_LO + so, Vlo + g);
    }
}

__global__ __launch_bounds__(128, 4)
void flash_attn_mma(const bf16* __restrict__ Qhi, const bf16* __restrict__ Qlo,
                    const bf16* __restrict__ Khi, const bf16* __restrict__ Klo,
                    const bf16* __restrict__ Vhi, const bf16* __restrict__ Vlo,
                    bf16* __restrict__ Chi, bf16* __restrict__ Clo)
{
    __shared__ __align__(128) char smem[ATT_SMEM];
    uint32_t sb = smem_u32(smem);
    const int tid  = threadIdx.x;
    const int lane = tid & 31;
    const int wid  = tid >> 5;
    const int q0 = blockIdx.x * 64;
    const int h  = blockIdx.y;
    const int b  = blockIdx.z;

    const size_t qg  = ((size_t)(b * SEQ + q0)) * HID + h * HDIM;
    const size_t kvg = ((size_t)(b * SEQ)) * HID + h * HDIM;

    // Load Q tile (64 rows x 64 bf16, hi & lo) -> group 0
    #pragma unroll
    for (int r = 0; r < 4; r++) {
        int u = r * 128 + tid;
        int row = u >> 3, seg = u & 7;
        uint32_t so = SW128((uint32_t)(row * 128 + seg * 16));
        cp16(sb + SQ_HI + so, Qhi + qg + (size_t)row * HID + seg * 8);
        cp16(sb + SQ_LO + so, Qlo + qg + (size_t)row * HID + seg * 8);
    }
    CP_COMMIT();

    // Load KV tile 0 -> stage 0 (group 1)
    att_load_kv(sb + STG0, kvg, Khi, Klo, Vhi, Vlo, tid);
    CP_COMMIT();

    const int wm = wid * 16;
    const int a_r    = (lane & 7) + ((lane >> 3) & 1) * 8;
    const int a_kb16 = (lane >> 4) * 16;
    const int b_r    = lane & 7;
    const int b_kb16 = ((lane >> 3) & 1) * 16;

    CP_WAIT1();              // Q resident (KV0 may be in flight)
    __syncthreads();

    // Cache only Q-hi A-fragments (4 k16-chunks); Q-lo reloaded on use.
    uint32_t qh[4][4];
    #pragma unroll
    for (int kc = 0; kc < 4; kc++) {
        int row = wm + a_r;
        uint32_t col = (uint32_t)((kc * 32 + a_kb16) ^ ((row & 7) << 4));
        ldsm4(qh[kc], sb + SQ_HI + (uint32_t)(row * 128) + col);
    }

    float m0 = -INFINITY, m1 = -INFINITY, l0 = 0.0f, l1 = 0.0f;
    float o[8][4];
    #pragma unroll
    for (int nt = 0; nt < 8; nt++)
        #pragma unroll
        for (int i = 0; i < 4; i++) o[nt][i] = 0.0f;

    for (int kt = 0; kt < SEQ / KT; kt++) {
        // Prefetch next tile into the other stage
        if (kt + 1 < SEQ / KT) {
            att_load_kv(sb + STG0 + ((kt + 1) & 1) * STG_SZ,
                        kvg + (size_t)((kt + 1) * KT) * HID,
                        Khi, Klo, Vhi, Vlo, tid);
            CP_COMMIT();
            CP_WAIT1();      // tile kt resident
        } else {
            CP_WAIT0();
        }
        __syncthreads();

        const uint32_t stg = sb + STG0 + (kt & 1) * STG_SZ;

        // ---- S = Q @ K^T (3 split terms), 32 keys ----
        float s[4][4];
        #pragma unroll
        for (int nt = 0; nt < 4; nt++)
            #pragma unroll
            for (int i = 0; i < 4; i++) s[nt][i] = 0.0f;

        #pragma unroll
        for (int kc = 0; kc < 4; kc++) {
            // Reload Q-lo fragment for this k-chunk from persistent Q smem
            uint32_t qlt[4];
            {
                int row = wm + a_r;
                uint32_t col = (uint32_t)((kc * 32 + a_kb16) ^ ((row & 7) << 4));
                ldsm4(qlt, sb + SQ_LO + (uint32_t)(row * 128) + col);
            }
            #pragma unroll
            for (int ntp = 0; ntp < 2; ntp++) {
                int nrow = ntp * 16 + ((lane >> 4) & 1) * 8 + b_r;
                uint32_t col = (uint32_t)((kc * 32 + b_kb16) ^ ((nrow & 7) << 4));
                uint32_t kh[4], kl[4];
                ldsm4(kh, stg + SK_HI + (uint32_t)(nrow * 128) + col);
                ldsm4(kl, stg + SK_LO + (uint32_t)(nrow * 128) + col);
                mma16816(s[2 * ntp],     qh[kc], kh);
                mma16816(s[2 * ntp],     qh[kc], kl);
                mma16816(s[2 * ntp],     qlt,    kh);
                mma16816(s[2 * ntp + 1], qh[kc], kh + 2);
                mma16816(s[2 * ntp + 1], qh[kc], kl + 2);
                mma16816(s[2 * ntp + 1], qlt,    kh + 2);
            }
        }

        // ---- Online softmax ----
        float rmax0 = -INFINITY, rmax1 = -INFINITY;
        #pragma unroll
        for (int nt = 0; nt < 4; nt++) {
            rmax0 = fmaxf(rmax0, fmaxf(s[nt][0], s[nt][1]));
            rmax1 = fmaxf(rmax1, fmaxf(s[nt][2], s[nt][3]));
        }
        rmax0 = fmaxf(rmax0, __shfl_xor_sync(0xffffffffu, rmax0, 1));
        rmax0 = fmaxf(rmax0, __shfl_xor_sync(0xffffffffu, rmax0, 2));
        rmax1 = fmaxf(rmax1, __shfl_xor_sync(0xffffffffu, rmax1, 1));
        rmax1 = fmaxf(rmax1, __shfl_xor_sync(0xffffffffu, rmax1, 2));

        float mt0 = fmaxf(m0, rmax0), mt1 = fmaxf(m1, rmax1);
        float f0 = __expf(m0 - mt0),  f1 = __expf(m1 - mt1);
        m0 = mt0; m1 = mt1;

        float ls0 = 0.0f, ls1 = 0.0f;
        #pragma unroll
        for (int nt = 0; nt < 4; nt++) {
            s[nt][0] = __expf(s[nt][0] - m0);
            s[nt][1] = __expf(s[nt][1] - m0);
            s[nt][2] = __expf(s[nt][2] - m1);
            s[nt][3] = __expf(s[nt][3] - m1);
            ls0 += s[nt][0] + s[nt][1];
            ls1 += s[nt][2] + s[nt][3];
        }
        ls0 += __shfl_xor_sync(0xffffffffu, ls0, 1);
        ls0 += __shfl_xor_sync(0xffffffffu, ls0, 2);
        ls1 += __shfl_xor_sync(0xffffffffu, ls1, 1);
        ls1 += __shfl_xor_sync(0xffffffffu, ls1, 2);
        l0 = l0 * f0 + ls0;
        l1 = l1 * f1 + ls1;

        #pragma unroll
        for (int nt = 0; nt < 8; nt++) {
            o[nt][0] *= f0; o[nt][1] *= f0;
            o[nt][2] *= f1; o[nt][3] *= f1;
        }

        // ---- Pack P into A-fragments (hi + lo split) ----
        uint32_t phi[2][4], plo[2][4];
        #pragma unroll
        for (int kj = 0; kj < 2; kj++) {
            #pragma unroll
            for (int half = 0; half < 2; half++) {
                int t = 2 * kj + half;
                bf162 h0 = __floats2bfloat162_rn(s[t][0], s[t][1]);
                float2 hf0 = __bfloat1622float2(h0);
                bf162 lo0 = __floats2bfloat162_rn(s[t][0] - hf0.x, s[t][1] - hf0.y);
                bf162 h1 = __floats2bfloat162_rn(s[t][2], s[t][3]);
                float2 hf1 = __bfloat1622float2(h1);
                bf162 lo1 = __floats2bfloat162_rn(s[t][2] - hf1.x, s[t][3] - hf1.y);
                phi[kj][2 * half + 0] = *(uint32_t*)&h0;
                phi[kj][2 * half + 1] = *(uint32_t*)&h1;
                plo[kj][2 * half + 0] = *(uint32_t*)&lo0;
                plo[kj][2 * half + 1] = *(uint32_t*)&lo1;
            }
        }

        // ---- O += P @ V (3 split terms), V via ldmatrix.trans ----
        #pragma unroll
        for (int kj = 0; kj < 2; kj++) {
            #pragma unroll
            for (int ntv = 0; ntv < 4; ntv++) {
                uint32_t voff = SW128((uint32_t)((kj * 16 + (lane & 15)) * 128 +
                                                 (ntv * 16 + 8 * (lane >> 4)) * 2));
                uint32_t vh[4], vl[4];
                ldsm4t(vh, stg + SV_HI + voff);
                ldsm4t(vl, stg + SV_LO + voff);
                mma16816(o[2 * ntv],     phi[kj], vh);
                mma16816(o[2 * ntv],     phi[kj], vl);
                mma16816(o[2 * ntv],     plo[kj], vh);
                mma16816(o[2 * ntv + 1], phi[kj], vh + 2);
                mma16816(o[2 * ntv + 1], phi[kj], vl + 2);
                mma16816(o[2 * ntv + 1], plo[kj], vh + 2);
            }
        }

        __syncthreads();   // all warps done reading before next prefetch overwrites
    }

    // ---- Finalize: divide by l, split to bf16 hi/lo, store ----
    const float inv0 = 1.0f / l0, inv1 = 1.0f / l1;
    const int row0 = q0 + wm + (lane >> 2);
    const int colb = (lane & 3) * 2;
    #pragma unroll
    for (int nt = 0; nt < 8; nt++) {
        {
            float vx = o[nt][0] * inv0, vy = o[nt][1] * inv0;
            size_t idx = ((size_t)(b * SEQ + row0)) * HID + h * HDIM + nt * 8 + colb;
            bf162 hi2 = __floats2bfloat162_rn(vx, vy);
            float2 hf = __bfloat1622float2(hi2);
            bf162 lo2 = __floats2bfloat162_rn(vx - hf.x, vy - hf.y);
            *(bf162*)&Chi[idx] = hi2;
            *(bf162*)&Clo[idx] = lo2;
        }
        {
            float vx = o[nt][2] * inv1, vy = o[nt][3] * inv1;
            size_t idx = ((size_t)(b * SEQ + row0 + 8)) * HID + h * HDIM + nt * 8 + colb;
            bf162 hi2 = __floats2bfloat162_rn(vx, vy);
            float2 hf = __bfloat1622float2(hi2);
            bf162 lo2 = __floats2bfloat162_rn(vx - hf.x, vy - hf.y);
            *(bf162*)&Chi[idx] = hi2;
            *(bf162*)&Clo[idx] = lo2;
        }
    }
}

// ---------------------------------------------------------------------------
// Launch (no cudaFuncSetAttribute, no dynamic smem)
// ---------------------------------------------------------------------------
extern "C" void kernel_launch(void* const* d_in, const int* in_sizes, int n_in,
                              void* d_out, int out_size)
{
    const float* x  = (const float*)d_in[0];
    const float* Wq = (const float*)d_in[1];
    const float* bq = (const float*)d_in[2];
    const float* Wk = (const float*)d_in[3];
    const float* bk = (const float*)d_in[4];
    const float* Wv = (const float*)d_in[5];
    const float* bv = (const float*)d_in[6];
    const float* Wo = (const float*)d_in[7];
    const float* bo = (const float*)d_in[8];
    float* out = (float*)d_out;

    bf16 *xhi, *xlo, *qhi, *qlo, *khi, *klo, *vhi, *vlo, *chi, *clo, *wt4hi, *wt4lo;
    cudaGetSymbolAddress((void**)&xhi, g_xhi);
    cudaGetSymbolAddress((void**)&xlo, g_xlo);
    cudaGetSymbolAddress((void**)&qhi, g_qhi);
    cudaGetSymbolAddress((void**)&qlo, g_qlo);
    cudaGetSymbolAddress((void**)&khi, g_khi);
    cudaGetSymbolAddress((void**)&klo, g_klo);
    cudaGetSymbolAddress((void**)&vhi, g_vhi);
    cudaGetSymbolAddress((void**)&vlo, g_vlo);
    cudaGetSymbolAddress((void**)&chi, g_chi);
    cudaGetSymbolAddress((void**)&clo, g_clo);
    cudaGetSymbolAddress((void**)&wt4hi, g_wt4hi);
    cudaGetSymbolAddress((void**)&wt4lo, g_wt4lo);

    const int n4x = MROWS * HID / 4;
    dim3 wtg(HID / 32, HID / 32, 4);
    dim3 wtb(32, 8);

    convert_split<<<2048, 256>>>((const float4*)x, (bf162*)xhi, (bf162*)xlo, n4x);
    convert_wt_all<<<wtg, wtb>>>(Wq, Wk, Wv, Wo, wt4hi, wt4lo);

    dim3 qkvgrid(48, MROWS / 128);   // (48, 64): 3 panels x 16 n-tiles
    gemm_qkv<<<qkvgrid, 256>>>(xhi, xlo, wt4hi, wt4lo, bq, bk, bv,
                               qhi, qlo, khi, klo, vhi, vlo);

    dim3 agrid(SEQ / 64, NHEAD, BATCH);   // (16, 16, 8)
    flash_attn_mma<<<agrid, 128>>>(qhi, qlo, khi, klo, vhi, vlo, chi, clo);

    dim3 ogrid(HID / 64, MROWS / 128);    // (16, 64)
    gemm_out<<<ogrid, 256>>>(chi, clo,
                             wt4hi + (size_t)3 * HID * HID,
                             wt4lo + (size_t)3 * HID * HID, bo, out);
}

// round 10
// speedup vs baseline: 9.1321x; 2.4832x over previous
#include <cuda_runtime.h>
#include <cuda_fp16.h>
#include <math.h>
#include <stdint.h>

// ---------------------------------------------------------------------------
// Problem constants
// ---------------------------------------------------------------------------
#define BATCH 8
#define SEQ   1024
#define HID   1024
#define NHEAD 16
#define HDIM  64
#define MROWS (BATCH * SEQ)   // 8192

// ---------------------------------------------------------------------------
// Scratch (device globals; no allocation allowed)
// ---------------------------------------------------------------------------
__device__ __half g_xh[MROWS * HID];
__device__ __half g_qh[MROWS * HID];
__device__ __half g_kh[MROWS * HID];
__device__ __half g_vh[MROWS * HID];
__device__ __half g_ch[MROWS * HID];
__device__ __half g_wt4[4 * HID * HID];   // transposed weights [N,K], 4 panels

// ---------------------------------------------------------------------------
// Helpers
// ---------------------------------------------------------------------------
__device__ __forceinline__ uint32_t smem_u32(const void* p) {
    uint32_t a;
    asm("{ .reg .u64 t; cvta.to.shared.u64 t, %1; cvt.u32.u64 %0, t; }"
        : "=r"(a) : "l"(p));
    return a;
}

#define SW128(o) ((o) ^ (((o) >> 3) & 0x70))

__device__ __forceinline__ void cp16(uint32_t smem, const void* g) {
    asm volatile("cp.async.cg.shared.global [%0], [%1], 16;" :: "r"(smem), "l"(g));
}
#define CP_COMMIT()  asm volatile("cp.async.commit_group;" ::: "memory")
#define CP_WAIT1()   asm volatile("cp.async.wait_group 1;" ::: "memory")
#define CP_WAIT0()   asm volatile("cp.async.wait_group 0;" ::: "memory")

__device__ __forceinline__ void ldsm4(uint32_t* r, uint32_t addr) {
    asm volatile("ldmatrix.sync.aligned.m8n8.x4.shared.b16 {%0,%1,%2,%3}, [%4];"
        : "=r"(r[0]), "=r"(r[1]), "=r"(r[2]), "=r"(r[3]) : "r"(addr));
}
__device__ __forceinline__ void ldsm4t(uint32_t* r, uint32_t addr) {
    asm volatile("ldmatrix.sync.aligned.m8n8.x4.trans.shared.b16 {%0,%1,%2,%3}, [%4];"
        : "=r"(r[0]), "=r"(r[1]), "=r"(r[2]), "=r"(r[3]) : "r"(addr));
}
__device__ __forceinline__ void mma16816(float* c, const uint32_t* a, const uint32_t* b) {
    asm volatile("mma.sync.aligned.m16n8k16.row.col.f32.f16.f16.f32 "
        "{%0,%1,%2,%3}, {%4,%5,%6,%7}, {%8,%9}, {%0,%1,%2,%3};"
        : "+f"(c[0]), "+f"(c[1]), "+f"(c[2]), "+f"(c[3])
        : "r"(a[0]), "r"(a[1]), "r"(a[2]), "r"(a[3]), "r"(b[0]), "r"(b[1]));
}

// ---------------------------------------------------------------------------
// Converts: fp32 -> fp16
// ---------------------------------------------------------------------------
__global__ void convert_x(const float4* __restrict__ in, __half2* __restrict__ out, int n4)
{
    for (int i = blockIdx.x * blockDim.x + threadIdx.x; i < n4; i += gridDim.x * blockDim.x) {
        float4 v = in[i];
        out[2 * i]     = __floats2half2_rn(v.x, v.y);
        out[2 * i + 1] = __floats2half2_rn(v.z, v.w);
    }
}

// Transpose + convert all 4 weights (grid.z selects weight).
__global__ void convert_wt_all(const float* __restrict__ W0, const float* __restrict__ W1,
                               const float* __restrict__ W2, const float* __restrict__ W3,
                               __half* __restrict__ t4)
{
    __shared__ float t[32][33];
    const int z = blockIdx.z;
    const float* W = (z == 0) ? W0 : (z == 1) ? W1 : (z == 2) ? W2 : W3;
    __half* to = t4 + (size_t)z * HID * HID;

    int n0 = blockIdx.x * 32, k0 = blockIdx.y * 32;
    int tx = threadIdx.x, ty = threadIdx.y;
    #pragma unroll
    for (int r = 0; r < 32; r += 8)
        t[ty + r][tx] = W[(size_t)(k0 + ty + r) * HID + n0 + tx];
    __syncthreads();
    #pragma unroll
    for (int r = 0; r < 32; r += 8)
        to[(size_t)(n0 + ty + r) * HID + k0 + tx] = __float2half_rn(t[tx][ty + r]);
}

// ---------------------------------------------------------------------------
// GEMM machinery (single-term fp16, fp32 accumulate)
// CTA tile 128x64, K-chunk 64 (one 128B row per matrix row), double-buffered.
// 8 warps = 4(m) x 2(n), warp tile 32x32.
// ---------------------------------------------------------------------------
#define GKC        64
#define NCHUNK     (HID / GKC)       // 16
#define OFF_B      16384
#define STAGE_BYTES 24576            // A 16K + B 8K
#define GEMM_SMEM  (2 * STAGE_BYTES) // 49152 (static)

__device__ __forceinline__ void load_chunk(uint32_t sbase,
    const __half* __restrict__ A, const __half* __restrict__ B,
    int by, int bx, int k0, int tid)
{
    // A: 128 rows x 64 fp16 (128B) = 1024 16B-units -> 4/thread
    #pragma unroll
    for (int r = 0; r < 4; r++) {
        int u   = r * 256 + tid;
        int m   = u >> 3;
        int seg = u & 7;
        uint32_t so = SW128((uint32_t)(m * 128 + seg * 16));
        cp16(sbase + so, A + (size_t)(by * 128 + m) * HID + k0 + seg * 8);
    }
    // B: 64 rows -> 512 units -> 2/thread
    #pragma unroll
    for (int r = 0; r < 2; r++) {
        int u   = r * 256 + tid;
        int n   = u >> 3;
        int seg = u & 7;
        uint32_t so = SW128((uint32_t)(n * 128 + seg * 16));
        cp16(sbase + OFF_B + so, B + (size_t)(bx * 64 + n) * HID + k0 + seg * 8);
    }
}

__device__ __forceinline__ void gemm_mainloop(uint32_t sb, float c[2][4][4],
    const __half* __restrict__ A, const __half* __restrict__ B,
    int by, int bx, int tid, int lane, int wid)
{
    const int wm = (wid & 3) * 32;
    const int wn = (wid >> 2) * 32;

    const int a_r    = (lane & 7) + ((lane >> 3) & 1) * 8;
    const int a_kb16 = (lane >> 4) * 16;
    const int b_r4   = ((lane >> 4) & 1) * 8 + (lane & 7);
    const int b_kb16 = ((lane >> 3) & 1) * 16;

    load_chunk(sb, A, B, by, bx, 0, tid);
    CP_COMMIT();

    for (int ch = 0; ch < NCHUNK; ch++) {
        const uint32_t sbase = sb + (ch & 1) * STAGE_BYTES;

        if (ch + 1 < NCHUNK) {
            load_chunk(sb + ((ch + 1) & 1) * STAGE_BYTES, A, B, by, bx, (ch + 1) * GKC, tid);
            CP_COMMIT();
            CP_WAIT1();
        } else {
            CP_WAIT0();
        }
        __syncthreads();

        const uint32_t ab = sbase;
        const uint32_t bb = sbase + OFF_B;

        #pragma unroll
        for (int ks = 0; ks < 4; ks++) {
            const int kb = ks * 32;

            uint32_t Ah[2][4];
            #pragma unroll
            for (int mt = 0; mt < 2; mt++) {
                int row = wm + mt * 16 + a_r;
                uint32_t col = (uint32_t)((kb + a_kb16) ^ ((row & 7) << 4));
                ldsm4(Ah[mt], ab + (uint32_t)(row * 128) + col);
            }

            #pragma unroll
            for (int ntp = 0; ntp < 2; ntp++) {
                int nrow = wn + ntp * 16 + b_r4;
                uint32_t col = (uint32_t)((kb + b_kb16) ^ ((nrow & 7) << 4));
                uint32_t Bh[4];
                ldsm4(Bh, bb + (uint32_t)(nrow * 128) + col);
                #pragma unroll
                for (int half = 0; half < 2; half++) {
                    int nt = 2 * ntp + half;
                    mma16816(c[0][nt], Ah[0], Bh + 2 * half);
                    mma16816(c[1][nt], Ah[1], Bh + 2 * half);
                }
            }
        }

        __syncthreads();
    }
}

// Fused Q/K/V projection: grid.x = 48 (panel = bx>>4), fp16 output.
// Q panel pre-scaled by 0.125*log2(e) so attention can use exp2.
__global__ __launch_bounds__(256)
void gemm_qkv(const __half* __restrict__ A, const __half* __restrict__ wt4,
              const float* __restrict__ bq, const float* __restrict__ bk,
              const float* __restrict__ bv,
              __half* __restrict__ q, __half* __restrict__ k, __half* __restrict__ v)
{
    __shared__ __align__(128) char smem[GEMM_SMEM];
    uint32_t sb = smem_u32(smem);
    const int tid  = threadIdx.x;
    const int lane = tid & 31;
    const int wid  = tid >> 5;
    const int panel = blockIdx.x >> 4;
    const int bx    = blockIdx.x & 15;
    const int by    = blockIdx.y;

    const __half* B = wt4 + (size_t)panel * HID * HID;
    const float* bias = (panel == 0) ? bq : (panel == 1) ? bk : bv;
    __half* O = (panel == 0) ? q : (panel == 1) ? k : v;
    const float scale = (panel == 0) ? 0.125f * 1.44269504f : 1.0f;

    float c[2][4][4];
    #pragma unroll
    for (int mt = 0; mt < 2; mt++)
        #pragma unroll
        for (int nt = 0; nt < 4; nt++)
            #pragma unroll
            for (int i = 0; i < 4; i++) c[mt][nt][i] = 0.0f;

    gemm_mainloop(sb, c, A, B, by, bx, tid, lane, wid);

    const int wm = (wid & 3) * 32;
    const int wn = (wid >> 2) * 32;
    const int crow0 = by * 128 + wm + (lane >> 2);
    const int ccol0 = bx * 64 + wn + (lane & 3) * 2;
    #pragma unroll
    for (int nt = 0; nt < 4; nt++) {
        float2 bb = *(const float2*)&bias[ccol0 + nt * 8];
        #pragma unroll
        for (int mt = 0; mt < 2; mt++) {
            #pragma unroll
            for (int h = 0; h < 2; h++) {
                int row = crow0 + mt * 16 + h * 8;
                float vx = (c[mt][nt][2 * h + 0] + bb.x) * scale;
                float vy = (c[mt][nt][2 * h + 1] + bb.y) * scale;
                *(__half2*)&O[(size_t)row * HID + ccol0 + nt * 8] = __floats2half2_rn(vx, vy);
            }
        }
    }
}

// O-projection GEMM: fp32 output + bias.
__global__ __launch_bounds__(256)
void gemm_out(const __half* __restrict__ A, const __half* __restrict__ B,
              const float* __restrict__ bias, float* __restrict__ Cf)
{
    __shared__ __align__(128) char smem[GEMM_SMEM];
    uint32_t sb = smem_u32(smem);
    const int tid  = threadIdx.x;
    const int lane = tid & 31;
    const int wid  = tid >> 5;
    const int bx = blockIdx.x, by = blockIdx.y;

    float c[2][4][4];
    #pragma unroll
    for (int mt = 0; mt < 2; mt++)
        #pragma unroll
        for (int nt = 0; nt < 4; nt++)
            #pragma unroll
            for (int i = 0; i < 4; i++) c[mt][nt][i] = 0.0f;

    gemm_mainloop(sb, c, A, B, by, bx, tid, lane, wid);

    const int wm = (wid & 3) * 32;
    const int wn = (wid >> 2) * 32;
    const int crow0 = by * 128 + wm + (lane >> 2);
    const int ccol0 = bx * 64 + wn + (lane & 3) * 2;
    #pragma unroll
    for (int nt = 0; nt < 4; nt++) {
        float2 bb = *(const float2*)&bias[ccol0 + nt * 8];
        #pragma unroll
        for (int mt = 0; mt < 2; mt++) {
            #pragma unroll
            for (int h = 0; h < 2; h++) {
                int row = crow0 + mt * 16 + h * 8;
                float2 v;
                v.x = c[mt][nt][2 * h + 0] + bb.x;
                v.y = c[mt][nt][2 * h + 1] + bb.y;
                *(float2*)&Cf[(size_t)row * HID + ccol0 + nt * 8] = v;
            }
        }
    }
}

// ---------------------------------------------------------------------------
// fp16 tensor-core flash attention, 64-key tiles, double-buffered K/V.
// Per CTA: 64 queries x one (b,h). 4 warps x 16 query rows.
// Scores arrive in log2 domain (Q pre-scaled by 0.125*log2 e) -> exp2f.
// smem: Q 8K + 2 stages x (K 8K + V 8K) = 40K static.
// ---------------------------------------------------------------------------
#define KT     64
#define ATT_Q   0
#define ATT_STG0 8192
#define ATT_STG_SZ 16384
#define ATT_V_OFF 8192
#define ATT_SMEM 40960

__device__ __forceinline__ void att_load_kv(uint32_t stg, size_t kvb,
    const __half* __restrict__ K, const __half* __restrict__ V, int tid)
{
    #pragma unroll
    for (int r = 0; r < 4; r++) {
        int u = r * 128 + tid;
        int row = u >> 3, seg = u & 7;
        uint32_t so = SW128((uint32_t)(row * 128 + seg * 16));
        const size_t g = kvb + (size_t)row * HID + seg * 8;
        cp16(stg + so, K + g);
        cp16(stg + ATT_V_OFF + so, V + g);
    }
}

__global__ __launch_bounds__(128, 4)
void flash_attn_mma(const __half* __restrict__ Q, const __half* __restrict__ K,
                    const __half* __restrict__ V, __half* __restrict__ C)
{
    __shared__ __align__(128) char smem[ATT_SMEM];
    uint32_t sb = smem_u32(smem);
    const int tid  = threadIdx.x;
    const int lane = tid & 31;
    const int wid  = tid >> 5;
    const int q0 = blockIdx.x * 64;
    const int h  = blockIdx.y;
    const int b  = blockIdx.z;

    const size_t qg  = ((size_t)(b * SEQ + q0)) * HID + h * HDIM;
    const size_t kvg = ((size_t)(b * SEQ)) * HID + h * HDIM;

    // Load Q tile (64 x 64 fp16) -> group 0
    #pragma unroll
    for (int r = 0; r < 4; r++) {
        int u = r * 128 + tid;
        int row = u >> 3, seg = u & 7;
        uint32_t so = SW128((uint32_t)(row * 128 + seg * 16));
        cp16(sb + ATT_Q + so, Q + qg + (size_t)row * HID + seg * 8);
    }
    CP_COMMIT();

    att_load_kv(sb + ATT_STG0, kvg, K, V, tid);
    CP_COMMIT();

    const int wm = wid * 16;
    const int a_r    = (lane & 7) + ((lane >> 3) & 1) * 8;
    const int a_kb16 = (lane >> 4) * 16;
    const int b_r    = lane & 7;
    const int b_kb16 = ((lane >> 3) & 1) * 16;

    CP_WAIT1();              // Q resident
    __syncthreads();

    // Cache Q A-fragments (4 k16-chunks)
    uint32_t qh[4][4];
    #pragma unroll
    for (int kc = 0; kc < 4; kc++) {
        int row = wm + a_r;
        uint32_t col = (uint32_t)((kc * 32 + a_kb16) ^ ((row & 7) << 4));
        ldsm4(qh[kc], sb + ATT_Q + (uint32_t)(row * 128) + col);
    }

    float m0 = -INFINITY, m1 = -INFINITY, l0 = 0.0f, l1 = 0.0f;
    float o[8][4];
    #pragma unroll
    for (int nt = 0; nt < 8; nt++)
        #pragma unroll
        for (int i = 0; i < 4; i++) o[nt][i] = 0.0f;

    for (int kt = 0; kt < SEQ / KT; kt++) {
        if (kt + 1 < SEQ / KT) {
            att_load_kv(sb + ATT_STG0 + ((kt + 1) & 1) * ATT_STG_SZ,
                        kvg + (size_t)((kt + 1) * KT) * HID, K, V, tid);
            CP_COMMIT();
            CP_WAIT1();
        } else {
            CP_WAIT0();
        }
        __syncthreads();

        const uint32_t stg = sb + ATT_STG0 + (kt & 1) * ATT_STG_SZ;

        // ---- S = Q @ K^T (log2-scaled scores) ----
        float s[8][4];
        #pragma unroll
        for (int nt = 0; nt < 8; nt++)
            #pragma unroll
            for (int i = 0; i < 4; i++) s[nt][i] = 0.0f;

        #pragma unroll
        for (int kc = 0; kc < 4; kc++) {
            #pragma unroll
            for (int ntp = 0; ntp < 4; ntp++) {
                int nrow = ntp * 16 + ((lane >> 4) & 1) * 8 + b_r;
                uint32_t col = (uint32_t)((kc * 32 + b_kb16) ^ ((nrow & 7) << 4));
                uint32_t kh[4];
                ldsm4(kh, stg + (uint32_t)(nrow * 128) + col);
                mma16816(s[2 * ntp],     qh[kc], kh);
                mma16816(s[2 * ntp + 1], qh[kc], kh + 2);
            }
        }

        // ---- Online softmax (base-2) ----
        float rmax0 = -INFINITY, rmax1 = -INFINITY;
        #pragma unroll
        for (int nt = 0; nt < 8; nt++) {
            rmax0 = fmaxf(rmax0, fmaxf(s[nt][0], s[nt][1]));
            rmax1 = fmaxf(rmax1, fmaxf(s[nt][2], s[nt][3]));
        }
        rmax0 = fmaxf(rmax0, __shfl_xor_sync(0xffffffffu, rmax0, 1));
        rmax0 = fmaxf(rmax0, __shfl_xor_sync(0xffffffffu, rmax0, 2));
        rmax1 = fmaxf(rmax1, __shfl_xor_sync(0xffffffffu, rmax1, 1));
        rmax1 = fmaxf(rmax1, __shfl_xor_sync(0xffffffffu, rmax1, 2));

        float mt0 = fmaxf(m0, rmax0), mt1 = fmaxf(m1, rmax1);
        float f0 = exp2f(m0 - mt0),  f1 = exp2f(m1 - mt1);
        m0 = mt0; m1 = mt1;

        float ls0 = 0.0f, ls1 = 0.0f;
        #pragma unroll
        for (int nt = 0; nt < 8; nt++) {
            s[nt][0] = exp2f(s[nt][0] - m0);
            s[nt][1] = exp2f(s[nt][1] - m0);
            s[nt][2] = exp2f(s[nt][2] - m1);
            s[nt][3] = exp2f(s[nt][3] - m1);
            ls0 += s[nt][0] + s[nt][1];
            ls1 += s[nt][2] + s[nt][3];
        }
        ls0 += __shfl_xor_sync(0xffffffffu, ls0, 1);
        ls0 += __shfl_xor_sync(0xffffffffu, ls0, 2);
        ls1 += __shfl_xor_sync(0xffffffffu, ls1, 1);
        ls1 += __shfl_xor_sync(0xffffffffu, ls1, 2);
        l0 = l0 * f0 + ls0;
        l1 = l1 * f1 + ls1;

        #pragma unroll
        for (int nt = 0; nt < 8; nt++) {
            o[nt][0] *= f0; o[nt][1] *= f0;
            o[nt][2] *= f1; o[nt][3] *= f1;
        }

        // ---- Pack P into fp16 A-fragments ----
        uint32_t phi[4][4];
        #pragma unroll
        for (int kj = 0; kj < 4; kj++) {
            #pragma unroll
            for (int half = 0; half < 2; half++) {
                int t = 2 * kj + half;
                __half2 h0 = __floats2half2_rn(s[t][0], s[t][1]);
                __half2 h1 = __floats2half2_rn(s[t][2], s[t][3]);
                phi[kj][2 * half + 0] = *(uint32_t*)&h0;
                phi[kj][2 * half + 1] = *(uint32_t*)&h1;
            }
        }

        // ---- O += P @ V (V via ldmatrix.trans) ----
        #pragma unroll
        for (int kj = 0; kj < 4; kj++) {
            #pragma unroll
            for (int ntv = 0; ntv < 4; ntv++) {
                uint32_t voff = SW128((uint32_t)((kj * 16 + (lane & 15)) * 128 +
                                                 (ntv * 16 + 8 * (lane >> 4)) * 2));
                uint32_t vh[4];
                ldsm4t(vh, stg + ATT_V_OFF + voff);
                mma16816(o[2 * ntv],     phi[kj], vh);
                mma16816(o[2 * ntv + 1], phi[kj], vh + 2);
            }
        }

        __syncthreads();
    }

    // ---- Finalize: divide by l, fp16 store ----
    const float inv0 = 1.0f / l0, inv1 = 1.0f / l1;
    const int row0 = q0 + wm + (lane >> 2);
    const int colb = (lane & 3) * 2;
    #pragma unroll
    for (int nt = 0; nt < 8; nt++) {
        {
            size_t idx = ((size_t)(b * SEQ + row0)) * HID + h * HDIM + nt * 8 + colb;
            *(__half2*)&C[idx] = __floats2half2_rn(o[nt][0] * inv0, o[nt][1] * inv0);
        }
        {
            size_t idx = ((size_t)(b * SEQ + row0 + 8)) * HID + h * HDIM + nt * 8 + colb;
            *(__half2*)&C[idx] = __floats2half2_rn(o[nt][2] * inv1, o[nt][3] * inv1);
        }
    }
}

// ---------------------------------------------------------------------------
// Launch (no cudaFuncSetAttribute, no dynamic smem)
// ---------------------------------------------------------------------------
extern "C" void kernel_launch(void* const* d_in, const int* in_sizes, int n_in,
                              void* d_out, int out_size)
{
    const float* x  = (const float*)d_in[0];
    const float* Wq = (const float*)d_in[1];
    const float* bq = (const float*)d_in[2];
    const float* Wk = (const float*)d_in[3];
    const float* bk = (const float*)d_in[4];
    const float* Wv = (const float*)d_in[5];
    const float* bv = (const float*)d_in[6];
    const float* Wo = (const float*)d_in[7];
    const float* bo = (const float*)d_in[8];
    float* out = (float*)d_out;

    __half *xh, *qh, *kh, *vh, *ch, *wt4;
    cudaGetSymbolAddress((void**)&xh, g_xh);
    cudaGetSymbolAddress((void**)&qh, g_qh);
    cudaGetSymbolAddress((void**)&kh, g_kh);
    cudaGetSymbolAddress((void**)&vh, g_vh);
    cudaGetSymbolAddress((void**)&ch, g_ch);
    cudaGetSymbolAddress((void**)&wt4, g_wt4);

    const int n4x = MROWS * HID / 4;
    dim3 wtg(HID / 32, HID / 32, 4);
    dim3 wtb(32, 8);

    convert_x<<<2048, 256>>>((const float4*)x, (__half2*)xh, n4x);
    convert_wt_all<<<wtg, wtb>>>(Wq, Wk, Wv, Wo, wt4);

    dim3 qkvgrid(48, MROWS / 128);   // (48, 64): 3 panels x 16 n-tiles
    gemm_qkv<<<qkvgrid, 256>>>(xh, wt4, bq, bk, bv, qh, kh, vh);

    dim3 agrid(SEQ / 64, NHEAD, BATCH);   // (16, 16, 8)
    flash_attn_mma<<<agrid, 128>>>(qh, kh, vh, ch);

    dim3 ogrid(HID / 64, MROWS / 128);    // (16, 64)
    gemm_out<<<ogrid, 256>>>(ch, wt4 + (size_t)3 * HID * HID, bo, out);
}

// round 12
// speedup vs baseline: 9.4141x; 1.0309x over previous
#include <cuda_runtime.h>
#include <cuda_fp16.h>
#include <math.h>
#include <stdint.h>

// ---------------------------------------------------------------------------
// Problem constants
// ---------------------------------------------------------------------------
#define BATCH 8
#define SEQ   1024
#define HID   1024
#define NHEAD 16
#define HDIM  64
#define MROWS (BATCH * SEQ)   // 8192

// ---------------------------------------------------------------------------
// Scratch (device globals; no allocation allowed)
// ---------------------------------------------------------------------------
__device__ __half g_xh[MROWS * HID];
__device__ __half g_qh[MROWS * HID];
__device__ __half g_kh[MROWS * HID];
__device__ __half g_vh[MROWS * HID];
__device__ __half g_ch[MROWS * HID];
__device__ __half g_wt4[4 * HID * HID];   // transposed weights [N,K], 4 panels

// ---------------------------------------------------------------------------
// Helpers
// ---------------------------------------------------------------------------
__device__ __forceinline__ uint32_t smem_u32(const void* p) {
    uint32_t a;
    asm("{ .reg .u64 t; cvta.to.shared.u64 t, %1; cvt.u32.u64 %0, t; }"
        : "=r"(a) : "l"(p));
    return a;
}

#define SW128(o) ((o) ^ (((o) >> 3) & 0x70))

__device__ __forceinline__ void cp16(uint32_t smem, const void* g) {
    asm volatile("cp.async.cg.shared.global [%0], [%1], 16;" :: "r"(smem), "l"(g));
}
#define CP_COMMIT()  asm volatile("cp.async.commit_group;" ::: "memory")
#define CP_WAIT1()   asm volatile("cp.async.wait_group 1;" ::: "memory")
#define CP_WAIT0()   asm volatile("cp.async.wait_group 0;" ::: "memory")

__device__ __forceinline__ void ldsm4(uint32_t* r, uint32_t addr) {
    asm volatile("ldmatrix.sync.aligned.m8n8.x4.shared.b16 {%0,%1,%2,%3}, [%4];"
        : "=r"(r[0]), "=r"(r[1]), "=r"(r[2]), "=r"(r[3]) : "r"(addr));
}
__device__ __forceinline__ void ldsm4t(uint32_t* r, uint32_t addr) {
    asm volatile("ldmatrix.sync.aligned.m8n8.x4.trans.shared.b16 {%0,%1,%2,%3}, [%4];"
        : "=r"(r[0]), "=r"(r[1]), "=r"(r[2]), "=r"(r[3]) : "r"(addr));
}
__device__ __forceinline__ void mma16816(float* c, const uint32_t* a, const uint32_t* b) {
    asm volatile("mma.sync.aligned.m16n8k16.row.col.f32.f16.f16.f32 "
        "{%0,%1,%2,%3}, {%4,%5,%6,%7}, {%8,%9}, {%0,%1,%2,%3};"
        : "+f"(c[0]), "+f"(c[1]), "+f"(c[2]), "+f"(c[3])
        : "r"(a[0]), "r"(a[1]), "r"(a[2]), "r"(a[3]), "r"(b[0]), "r"(b[1]));
}

// ---------------------------------------------------------------------------
// Converts: fp32 -> fp16
// ---------------------------------------------------------------------------
__global__ void convert_x(const float4* __restrict__ in, __half2* __restrict__ out, int n4)
{
    for (int i = blockIdx.x * blockDim.x + threadIdx.x; i < n4; i += gridDim.x * blockDim.x) {
        float4 v = in[i];
        out[2 * i]     = __floats2half2_rn(v.x, v.y);
        out[2 * i + 1] = __floats2half2_rn(v.z, v.w);
    }
}

// Transpose + convert all 4 weights (grid.z selects weight).
__global__ void convert_wt_all(const float* __restrict__ W0, const float* __restrict__ W1,
                               const float* __restrict__ W2, const float* __restrict__ W3,
                               __half* __restrict__ t4)
{
    __shared__ float t[32][33];
    const int z = blockIdx.z;
    const float* W = (z == 0) ? W0 : (z == 1) ? W1 : (z == 2) ? W2 : W3;
    __half* to = t4 + (size_t)z * HID * HID;

    int n0 = blockIdx.x * 32, k0 = blockIdx.y * 32;
    int tx = threadIdx.x, ty = threadIdx.y;
    #pragma unroll
    for (int r = 0; r < 32; r += 8)
        t[ty + r][tx] = W[(size_t)(k0 + ty + r) * HID + n0 + tx];
    __syncthreads();
    #pragma unroll
    for (int r = 0; r < 32; r += 8)
        to[(size_t)(n0 + ty + r) * HID + k0 + tx] = __float2half_rn(t[tx][ty + r]);
}

// ---------------------------------------------------------------------------
// GEMM machinery (single-term fp16, fp32 accumulate)
// CTA tile 128x64, K-chunk 64, double-buffered. 8 warps = 4(m) x 2(n).
// Load addresses: per-thread precomputed pointers + k0 offset.
// ---------------------------------------------------------------------------
#define GKC        64
#define NCHUNK     (HID / GKC)       // 16
#define OFF_B      16384
#define STAGE_BYTES 24576            // A 16K + B 8K
#define GEMM_SMEM  (2 * STAGE_BYTES) // 49152 (static)

__device__ __forceinline__ void gemm_mainloop(uint32_t sb, float c[2][4][4],
    const __half* __restrict__ A, const __half* __restrict__ B,
    int by, int bx, int tid, int lane, int wid)
{
    const int wm = (wid & 3) * 32;
    const int wn = (wid >> 2) * 32;

    const int a_r    = (lane & 7) + ((lane >> 3) & 1) * 8;
    const int a_kb16 = (lane >> 4) * 16;
    const int b_r4   = ((lane >> 4) & 1) * 8 + (lane & 7);
    const int b_kb16 = ((lane >> 3) & 1) * 16;

    // Precomputed per-thread load geometry (SW128 offsets + base pointers)
    uint32_t aso[4]; const __half* ap[4];
    #pragma unroll
    for (int r = 0; r < 4; r++) {
        int u = r * 256 + tid;
        int m = u >> 3, seg = u & 7;
        aso[r] = SW128((uint32_t)(m * 128 + seg * 16));
        ap[r]  = A + (size_t)(by * 128 + m) * HID + seg * 8;
    }
    uint32_t bso[2]; const __half* bp[2];
    #pragma unroll
    for (int r = 0; r < 2; r++) {
        int u = r * 256 + tid;
        int n = u >> 3, seg = u & 7;
        bso[r] = SW128((uint32_t)(n * 128 + seg * 16));
        bp[r]  = B + (size_t)(bx * 64 + n) * HID + seg * 8;
    }

    // Prologue: chunk 0
    #pragma unroll
    for (int r = 0; r < 4; r++) cp16(sb + aso[r], ap[r]);
    #pragma unroll
    for (int r = 0; r < 2; r++) cp16(sb + OFF_B + bso[r], bp[r]);
    CP_COMMIT();

    for (int ch = 0; ch < NCHUNK; ch++) {
        const uint32_t sbase = sb + (ch & 1) * STAGE_BYTES;

        if (ch + 1 < NCHUNK) {
            const uint32_t nb = sb + ((ch + 1) & 1) * STAGE_BYTES;
            const int k0 = (ch + 1) * GKC;
            #pragma unroll
            for (int r = 0; r < 4; r++) cp16(nb + aso[r], ap[r] + k0);
            #pragma unroll
            for (int r = 0; r < 2; r++) cp16(nb + OFF_B + bso[r], bp[r] + k0);
            CP_COMMIT();
            CP_WAIT1();
        } else {
            CP_WAIT0();
        }
        __syncthreads();

        const uint32_t ab = sbase;
        const uint32_t bb = sbase + OFF_B;

        #pragma unroll
        for (int ks = 0; ks < 4; ks++) {
            const int kb = ks * 32;

            uint32_t Ah[2][4];
            #pragma unroll
            for (int mt = 0; mt < 2; mt++) {
                int row = wm + mt * 16 + a_r;
                uint32_t col = (uint32_t)((kb + a_kb16) ^ ((row & 7) << 4));
                ldsm4(Ah[mt], ab + (uint32_t)(row * 128) + col);
            }

            #pragma unroll
            for (int ntp = 0; ntp < 2; ntp++) {
                int nrow = wn + ntp * 16 + b_r4;
                uint32_t col = (uint32_t)((kb + b_kb16) ^ ((nrow & 7) << 4));
                uint32_t Bh[4];
                ldsm4(Bh, bb + (uint32_t)(nrow * 128) + col);
                #pragma unroll
                for (int half = 0; half < 2; half++) {
                    int nt = 2 * ntp + half;
                    mma16816(c[0][nt], Ah[0], Bh + 2 * half);
                    mma16816(c[1][nt], Ah[1], Bh + 2 * half);
                }
            }
        }

        __syncthreads();
    }
}

// Fused Q/K/V projection: grid.x = 48 (panel = bx>>4), fp16 output.
// Q panel pre-scaled by 0.125*log2(e) so attention can use exp2.
__global__ __launch_bounds__(256)
void gemm_qkv(const __half* __restrict__ A, const __half* __restrict__ wt4,
              const float* __restrict__ bq, const float* __restrict__ bk,
              const float* __restrict__ bv,
              __half* __restrict__ q, __half* __restrict__ k, __half* __restrict__ v)
{
    __shared__ __align__(128) char smem[GEMM_SMEM];
    uint32_t sb = smem_u32(smem);
    const int tid  = threadIdx.x;
    const int lane = tid & 31;
    const int wid  = tid >> 5;
    const int panel = blockIdx.x >> 4;
    const int bx    = blockIdx.x & 15;
    const int by    = blockIdx.y;

    const __half* B = wt4 + (size_t)panel * HID * HID;
    const float* bias = (panel == 0) ? bq : (panel == 1) ? bk : bv;
    __half* O = (panel == 0) ? q : (panel == 1) ? k : v;
    const float scale = (panel == 0) ? 0.125f * 1.44269504f : 1.0f;

    float c[2][4][4];
    #pragma unroll
    for (int mt = 0; mt < 2; mt++)
        #pragma unroll
        for (int nt = 0; nt < 4; nt++)
            #pragma unroll
            for (int i = 0; i < 4; i++) c[mt][nt][i] = 0.0f;

    gemm_mainloop(sb, c, A, B, by, bx, tid, lane, wid);

    const int wm = (wid & 3) * 32;
    const int wn = (wid >> 2) * 32;
    const int crow0 = by * 128 + wm + (lane >> 2);
    const int ccol0 = bx * 64 + wn + (lane & 3) * 2;
    #pragma unroll
    for (int nt = 0; nt < 4; nt++) {
        float2 bb = *(const float2*)&bias[ccol0 + nt * 8];
        #pragma unroll
        for (int mt = 0; mt < 2; mt++) {
            #pragma unroll
            for (int h = 0; h < 2; h++) {
                int row = crow0 + mt * 16 + h * 8;
                float vx = (c[mt][nt][2 * h + 0] + bb.x) * scale;
                float vy = (c[mt][nt][2 * h + 1] + bb.y) * scale;
                *(__half2*)&O[(size_t)row * HID + ccol0 + nt * 8] = __floats2half2_rn(vx, vy);
            }
        }
    }
}

// O-projection GEMM: fp32 output + bias.
__global__ __launch_bounds__(256)
void gemm_out(const __half* __restrict__ A, const __half* __restrict__ B,
              const float* __restrict__ bias, float* __restrict__ Cf)
{
    __shared__ __align__(128) char smem[GEMM_SMEM];
    uint32_t sb = smem_u32(smem);
    const int tid  = threadIdx.x;
    const int lane = tid & 31;
    const int wid  = tid >> 5;
    const int bx = blockIdx.x, by = blockIdx.y;

    float c[2][4][4];
    #pragma unroll
    for (int mt = 0; mt < 2; mt++)
        #pragma unroll
        for (int nt = 0; nt < 4; nt++)
            #pragma unroll
            for (int i = 0; i < 4; i++) c[mt][nt][i] = 0.0f;

    gemm_mainloop(sb, c, A, B, by, bx, tid, lane, wid);

    const int wm = (wid & 3) * 32;
    const int wn = (wid >> 2) * 32;
    const int crow0 = by * 128 + wm + (lane >> 2);
    const int ccol0 = bx * 64 + wn + (lane & 3) * 2;
    #pragma unroll
    for (int nt = 0; nt < 4; nt++) {
        float2 bb = *(const float2*)&bias[ccol0 + nt * 8];
        #pragma unroll
        for (int mt = 0; mt < 2; mt++) {
            #pragma unroll
            for (int h = 0; h < 2; h++) {
                int row = crow0 + mt * 16 + h * 8;
                float2 v;
                v.x = c[mt][nt][2 * h + 0] + bb.x;
                v.y = c[mt][nt][2 * h + 1] + bb.y;
                *(float2*)&Cf[(size_t)row * HID + ccol0 + nt * 8] = v;
            }
        }
    }
}

// ---------------------------------------------------------------------------
// fp16 tensor-core flash attention, 64-key tiles, double-buffered K/V.
// Per CTA: 128 queries x one (b,h). 8 warps x 16 query rows (256 threads).
// smem: Q 16K + 2 stages x (K 8K + V 8K) = 48K static (at the cap).
// ---------------------------------------------------------------------------
#define KT     64
#define ATT_Q   0
#define ATT_STG0 16384
#define ATT_STG_SZ 16384
#define ATT_V_OFF 8192
#define ATT_SMEM 49152

__global__ __launch_bounds__(256, 2)
void flash_attn_mma(const __half* __restrict__ Q, const __half* __restrict__ K,
                    const __half* __restrict__ V, __half* __restrict__ C)
{
    __shared__ __align__(128) char smem[ATT_SMEM];
    uint32_t sb = smem_u32(smem);
    const int tid  = threadIdx.x;
    const int lane = tid & 31;
    const int wid  = tid >> 5;
    const int q0 = blockIdx.x * 128;
    const int h  = blockIdx.y;
    const int b  = blockIdx.z;

    const size_t qg  = ((size_t)(b * SEQ + q0)) * HID + h * HDIM;
    const size_t kvg = ((size_t)(b * SEQ)) * HID + h * HDIM;

    // ---- Q load: 128 rows x 8 segs = 1024 units -> 4/thread ----
    {
        #pragma unroll
        for (int r = 0; r < 4; r++) {
            int u = r * 256 + tid;
            int row = u >> 3, seg = u & 7;
            uint32_t so = SW128((uint32_t)(row * 128 + seg * 16));
            cp16(sb + ATT_Q + so, Q + qg + (size_t)row * HID + seg * 8);
        }
    }
    CP_COMMIT();

    // K/V: 64 rows x 8 segs = 512 units each -> 2/thread each
    uint32_t kvso[2];
    const __half* kp[2];
    const __half* vp[2];
    #pragma unroll
    for (int r = 0; r < 2; r++) {
        int u = r * 256 + tid;
        int row = u >> 3, seg = u & 7;
        kvso[r] = SW128((uint32_t)(row * 128 + seg * 16));
        size_t off = kvg + (size_t)row * HID + seg * 8;
        kp[r] = K + off;
        vp[r] = V + off;
    }

    // KV tile 0 -> stage 0
    #pragma unroll
    for (int r = 0; r < 2; r++) {
        cp16(sb + ATT_STG0 + kvso[r], kp[r]);
        cp16(sb + ATT_STG0 + ATT_V_OFF + kvso[r], vp[r]);
    }
    CP_COMMIT();
    #pragma unroll
    for (int r = 0; r < 2; r++) { kp[r] += KT * HID; vp[r] += KT * HID; }

    const int wm = wid * 16;
    const int a_r    = (lane & 7) + ((lane >> 3) & 1) * 8;
    const int a_kb16 = (lane >> 4) * 16;
    const int b_r    = lane & 7;
    const int b_kb16 = ((lane >> 3) & 1) * 16;

    CP_WAIT1();              // Q resident
    __syncthreads();

    // Cache Q A-fragments (4 k16-chunks)
    uint32_t qh[4][4];
    #pragma unroll
    for (int kc = 0; kc < 4; kc++) {
        int row = wm + a_r;
        uint32_t col = (uint32_t)((kc * 32 + a_kb16) ^ ((row & 7) << 4));
        ldsm4(qh[kc], sb + ATT_Q + (uint32_t)(row * 128) + col);
    }

    float m0 = -INFINITY, m1 = -INFINITY, l0 = 0.0f, l1 = 0.0f;
    float o[8][4];
    #pragma unroll
    for (int nt = 0; nt < 8; nt++)
        #pragma unroll
        for (int i = 0; i < 4; i++) o[nt][i] = 0.0f;

    for (int kt = 0; kt < SEQ / KT; kt++) {
        if (kt + 1 < SEQ / KT) {
            const uint32_t nstg = sb + ATT_STG0 + ((kt + 1) & 1) * ATT_STG_SZ;
            #pragma unroll
            for (int r = 0; r < 2; r++) {
                cp16(nstg + kvso[r], kp[r]);
                cp16(nstg + ATT_V_OFF + kvso[r], vp[r]);
            }
            CP_COMMIT();
            #pragma unroll
            for (int r = 0; r < 2; r++) { kp[r] += KT * HID; vp[r] += KT * HID; }
            CP_WAIT1();
        } else {
            CP_WAIT0();
        }
        __syncthreads();

        const uint32_t stg = sb + ATT_STG0 + (kt & 1) * ATT_STG_SZ;

        // ---- S = Q @ K^T (log2-scaled scores) ----
        float s[8][4];
        #pragma unroll
        for (int nt = 0; nt < 8; nt++)
            #pragma unroll
            for (int i = 0; i < 4; i++) s[nt][i] = 0.0f;

        #pragma unroll
        for (int kc = 0; kc < 4; kc++) {
            #pragma unroll
            for (int ntp = 0; ntp < 4; ntp++) {
                int nrow = ntp * 16 + ((lane >> 4) & 1) * 8 + b_r;
                uint32_t col = (uint32_t)((kc * 32 + b_kb16) ^ ((nrow & 7) << 4));
                uint32_t kh[4];
                ldsm4(kh, stg + (uint32_t)(nrow * 128) + col);
                mma16816(s[2 * ntp],     qh[kc], kh);
                mma16816(s[2 * ntp + 1], qh[kc], kh + 2);
            }
        }

        // ---- Online softmax (base-2) ----
        float rmax0 = -INFINITY, rmax1 = -INFINITY;
        #pragma unroll
        for (int nt = 0; nt < 8; nt++) {
            rmax0 = fmaxf(rmax0, fmaxf(s[nt][0], s[nt][1]));
            rmax1 = fmaxf(rmax1, fmaxf(s[nt][2], s[nt][3]));
        }
        rmax0 = fmaxf(rmax0, __shfl_xor_sync(0xffffffffu, rmax0, 1));
        rmax0 = fmaxf(rmax0, __shfl_xor_sync(0xffffffffu, rmax0, 2));
        rmax1 = fmaxf(rmax1, __shfl_xor_sync(0xffffffffu, rmax1, 1));
        rmax1 = fmaxf(rmax1, __shfl_xor_sync(0xffffffffu, rmax1, 2));

        float mt0 = fmaxf(m0, rmax0), mt1 = fmaxf(m1, rmax1);
        float f0 = exp2f(m0 - mt0),  f1 = exp2f(m1 - mt1);
        m0 = mt0; m1 = mt1;

        float ls0 = 0.0f, ls1 = 0.0f;
        #pragma unroll
        for (int nt = 0; nt < 8; nt++) {
            s[nt][0] = exp2f(s[nt][0] - m0);
            s[nt][1] = exp2f(s[nt][1] - m0);
            s[nt][2] = exp2f(s[nt][2] - m1);
            s[nt][3] = exp2f(s[nt][3] - m1);
            ls0 += s[nt][0] + s[nt][1];
            ls1 += s[nt][2] + s[nt][3];
        }
        ls0 += __shfl_xor_sync(0xffffffffu, ls0, 1);
        ls0 += __shfl_xor_sync(0xffffffffu, ls0, 2);
        ls1 += __shfl_xor_sync(0xffffffffu, ls1, 1);
        ls1 += __shfl_xor_sync(0xffffffffu, ls1, 2);
        l0 = l0 * f0 + ls0;
        l1 = l1 * f1 + ls1;

        #pragma unroll
        for (int nt = 0; nt < 8; nt++) {
            o[nt][0] *= f0; o[nt][1] *= f0;
            o[nt][2] *= f1; o[nt][3] *= f1;
        }

        // ---- Pack P into fp16 A-fragments ----
        uint32_t phi[4][4];
        #pragma unroll
        for (int kj = 0; kj < 4; kj++) {
            #pragma unroll
            for (int half = 0; half < 2; half++) {
                int t = 2 * kj + half;
                __half2 h0 = __floats2half2_rn(s[t][0], s[t][1]);
                __half2 h1 = __floats2half2_rn(s[t][2], s[t][3]);
                phi[kj][2 * half + 0] = *(uint32_t*)&h0;
                phi[kj][2 * half + 1] = *(uint32_t*)&h1;
            }
        }

        // ---- O += P @ V (V via ldmatrix.trans) ----
        #pragma unroll
        for (int kj = 0; kj < 4; kj++) {
            #pragma unroll
            for (int ntv = 0; ntv < 4; ntv++) {
                uint32_t voff = SW128((uint32_t)((kj * 16 + (lane & 15)) * 128 +
                                                 (ntv * 16 + 8 * (lane >> 4)) * 2));
                uint32_t vh[4];
                ldsm4t(vh, stg + ATT_V_OFF + voff);
                mma16816(o[2 * ntv],     phi[kj], vh);
                mma16816(o[2 * ntv + 1], phi[kj], vh + 2);
            }
        }

        __syncthreads();
    }

    // ---- Finalize: divide by l, fp16 store ----
    const float inv0 = 1.0f / l0, inv1 = 1.0f / l1;
    const int row0 = q0 + wm + (lane >> 2);
    const int colb = (lane & 3) * 2;
    #pragma unroll
    for (int nt = 0; nt < 8; nt++) {
        {
            size_t idx = ((size_t)(b * SEQ + row0)) * HID + h * HDIM + nt * 8 + colb;
            *(__half2*)&C[idx] = __floats2half2_rn(o[nt][0] * inv0, o[nt][1] * inv0);
        }
        {
            size_t idx = ((size_t)(b * SEQ + row0 + 8)) * HID + h * HDIM + nt * 8 + colb;
            *(__half2*)&C[idx] = __floats2half2_rn(o[nt][2] * inv1, o[nt][3] * inv1);
        }
    }
}

// ---------------------------------------------------------------------------
// Launch (no cudaFuncSetAttribute, no dynamic smem)
// ---------------------------------------------------------------------------
extern "C" void kernel_launch(void* const* d_in, const int* in_sizes, int n_in,
                              void* d_out, int out_size)
{
    const float* x  = (const float*)d_in[0];
    const float* Wq = (const float*)d_in[1];
    const float* bq = (const float*)d_in[2];
    const float* Wk = (const float*)d_in[3];
    const float* bk = (const float*)d_in[4];
    const float* Wv = (const float*)d_in[5];
    const float* bv = (const float*)d_in[6];
    const float* Wo = (const float*)d_in[7];
    const float* bo = (const float*)d_in[8];
    float* out = (float*)d_out;

    __half *xh, *qh, *kh, *vh, *ch, *wt4;
    cudaGetSymbolAddress((void**)&xh, g_xh);
    cudaGetSymbolAddress((void**)&qh, g_qh);
    cudaGetSymbolAddress((void**)&kh, g_kh);
    cudaGetSymbolAddress((void**)&vh, g_vh);
    cudaGetSymbolAddress((void**)&ch, g_ch);
    cudaGetSymbolAddress((void**)&wt4, g_wt4);

    const int n4x = MROWS * HID / 4;
    dim3 wtg(HID / 32, HID / 32, 4);
    dim3 wtb(32, 8);

    convert_x<<<2048, 256>>>((const float4*)x, (__half2*)xh, n4x);
    convert_wt_all<<<wtg, wtb>>>(Wq, Wk, Wv, Wo, wt4);

    dim3 qkvgrid(48, MROWS / 128);   // (48, 64): 3 panels x 16 n-tiles
    gemm_qkv<<<qkvgrid, 256>>>(xh, wt4, bq, bk, bv, qh, kh, vh);

    dim3 agrid(SEQ / 128, NHEAD, BATCH);   // (8, 16, 8)
    flash_attn_mma<<<agrid, 256>>>(qh, kh, vh, ch);

    dim3 ogrid(HID / 64, MROWS / 128);    // (16, 64)
    gemm_out<<<ogrid, 256>>>(ch, wt4 + (size_t)3 * HID * HID, bo, out);
}